// round 11
// baseline (speedup 1.0000x reference)
#include <cuda_runtime.h>
#include <cuda_bf16.h>
#include <cstdint>

typedef __nv_bfloat16 bf16;

#define M_TOK   32768
#define D_DIM   128
#define N_ATT   10
#define GRAV    0.001f
#define STEPSZ  0.01f
#define N_ITERS 50

#define OUT_FIELD_ELEMS (M_TOK * 128)
#define OUT_REC_ELEMS   (M_TOK * 100)

// ---------------- device scratch (allocation-free rule) --------------------
__device__ bf16  g_Hhi[M_TOK * 256], g_Hlo[M_TOK * 256];   // hidden (enc1/dec1 out)
__device__ float g_EMB[M_TOK * 128];                       // enc2 out (fp32)
__device__ bf16  g_W1hi[256 * 128], g_W1lo[256 * 128];     // [N,Kpad] K-major
__device__ bf16  g_W2hi[128 * 256], g_W2lo[128 * 256];
__device__ bf16  g_W3hi[256 * 128], g_W3lo[256 * 128];
__device__ bf16  g_W4hi[128 * 256], g_W4lo[128 * 256];     // N 100->128 padded
__device__ float g_Gram[N_ATT * N_ATT];
__device__ float g_change;

// ---------------- helpers ---------------------------------------------------
__device__ __forceinline__ uint32_t smem_u32(const void* p) {
    uint32_t a;
    asm("{ .reg .u64 t; cvta.to.shared.u64 t, %1; cvt.u32.u64 %0, t; }" : "=r"(a) : "l"(p));
    return a;
}
#define SWZ(off) ((off) ^ (((off) >> 3) & 0x70))

#define CP_ASYNC16(dst, src) \
    asm volatile("cp.async.ca.shared.global [%0], [%1], 16;" :: "r"(dst), "l"(src))
#define CP_COMMIT() asm volatile("cp.async.commit_group;" ::: "memory")
#define CP_WAIT1()  asm volatile("cp.async.wait_group 1;" ::: "memory")
#define CP_WAIT0()  asm volatile("cp.async.wait_group 0;" ::: "memory")

#define LDSM_X4(r0, r1, r2, r3, addr) \
    asm volatile("ldmatrix.sync.aligned.m8n8.x4.shared.b16 {%0,%1,%2,%3}, [%4];" \
        : "=r"(r0), "=r"(r1), "=r"(r2), "=r"(r3) : "r"(addr))

#define MMA16816(d, a0, a1, a2, a3, b0, b1) \
    asm volatile("mma.sync.aligned.m16n8k16.row.col.f32.bf16.bf16.f32 " \
        "{%0,%1,%2,%3}, {%4,%5,%6,%7}, {%8,%9}, {%0,%1,%2,%3};" \
        : "+f"((d)[0]), "+f"((d)[1]), "+f"((d)[2]), "+f"((d)[3]) \
        : "r"(a0), "r"(a1), "r"(a2), "r"(a3), "r"(b0), "r"(b1))

__device__ __forceinline__ void split2(float v, bf16& hi, bf16& lo) {
    hi = __float2bfloat16(v);
    lo = __float2bfloat16(v - __bfloat162float(hi));
}

// lo-part of truncation split, packed bf16x2 for a float pair
__device__ __forceinline__ uint32_t lo_pack2(float a, float b) {
    float ha = __uint_as_float(__float_as_uint(a) & 0xFFFF0000u);
    float hb = __uint_as_float(__float_as_uint(b) & 0xFFFF0000u);
    __nv_bfloat162 p = __float22bfloat162_rn(make_float2(a - ha, b - hb));
    return *reinterpret_cast<uint32_t*>(&p);
}

// ---------------------------------------------------------------------------
// bf16x3-split tensor-core GEMM, cp.async double-buffered.
// AFP32=true: A is fp32 in gmem; loader LDGs fp32, splits hi(trunc)/lo on the
// fly (register double-buffered), STS bf16 tiles. B always pre-split bf16 via
// cp.async. AFP32=false: A pre-split bf16 via cp.async (proven R9 path).
// CTA: 256 threads = 8 warps (4M x 2N), warp tile 32x32, CTA tile 128x64.
// Augmented K chunks of 64: [hi*hi | hi*lo | lo*hi], fp32 accumulation.
// ---------------------------------------------------------------------------
#define STAGE_BYTES 24576   // 16K A + 8K B, 1024-aligned

template<bool AFP32, bool RELU, bool SPLIT>
__global__ __launch_bounds__(256)
void mma_gemm(const float* __restrict__ Af, int Kact,
              const bf16* __restrict__ Ahi, const bf16* __restrict__ Alo, int lda,
              const bf16* __restrict__ Bhi, const bf16* __restrict__ Blo, int ldb,
              const float* __restrict__ bias,
              float* __restrict__ Cf, bf16* __restrict__ Chi, bf16* __restrict__ Clo,
              int ldc, int N_out, int nc)
{
    __shared__ alignas(1024) char smem[2 * STAGE_BYTES];
    const uint32_t sbase = smem_u32(smem);

    const int tid = threadIdx.x;
    const int wid = tid >> 5, lid = tid & 31;
    const int bm = blockIdx.x * 128, bn = blockIdx.y * 64;
    const int warpM = wid >> 1, warpN = wid & 1;
    const int m_base = warpM * 32, n_base = warpN * 32;
    const int phase = lid >> 3, r_in = lid & 7;
    const int lr = tid >> 3, lc = tid & 7;          // cp.async mapping
    const int r_ld = tid >> 1, halfsel = tid & 1;   // fp32-A loader mapping

    const int nch = 3 * nc;

    float acc[2][4][4];
    #pragma unroll
    for (int mt = 0; mt < 2; mt++)
        #pragma unroll
        for (int nt = 0; nt < 4; nt++)
            #pragma unroll
            for (int e = 0; e < 4; e++) acc[mt][nt][e] = 0.f;

    uint4 u[4], u2[4];

    // fp32 A: load 8 float4 (one 256B row-half), split to 4 uint4 bf16 tiles
    auto ldgcvtA = [&](int c, uint4* uu) {
        int ka = c & (nc - 1);
        bool lomode = (c >= 2 * nc);
        int kbase = ka * 64;
        const float* Arow = Af + (size_t)(bm + r_ld) * lda;
        #pragma unroll
        for (int j = 0; j < 4; j++) {
            int s = 4 * halfsel + j;
            int c0 = kbase + 8 * s;
            float4 f0 = make_float4(0.f, 0.f, 0.f, 0.f), f1 = f0;
            if (c0 < Kact)     f0 = *reinterpret_cast<const float4*>(Arow + c0);
            if (c0 + 4 < Kact) f1 = *reinterpret_cast<const float4*>(Arow + c0 + 4);
            if (!lomode) {
                uu[j].x = __byte_perm(__float_as_uint(f0.x), __float_as_uint(f0.y), 0x7632);
                uu[j].y = __byte_perm(__float_as_uint(f0.z), __float_as_uint(f0.w), 0x7632);
                uu[j].z = __byte_perm(__float_as_uint(f1.x), __float_as_uint(f1.y), 0x7632);
                uu[j].w = __byte_perm(__float_as_uint(f1.z), __float_as_uint(f1.w), 0x7632);
            } else {
                uu[j].x = lo_pack2(f0.x, f0.y);
                uu[j].y = lo_pack2(f0.z, f0.w);
                uu[j].z = lo_pack2(f1.x, f1.y);
                uu[j].w = lo_pack2(f1.z, f1.w);
            }
        }
    };
    auto stsA = [&](const uint4* uu, int st) {
        char* base = smem + st * STAGE_BYTES;
        #pragma unroll
        for (int j = 0; j < 4; j++) {
            int s = 4 * halfsel + j;
            *reinterpret_cast<uint4*>(base + SWZ(r_ld * 128 + s * 16)) = uu[j];
        }
    };
    // B-only cp.async (AFP32 mode)
    auto issueB = [&](int c, int st) {
        const bf16* Bb = (c >= nc && c < 2 * nc) ? Blo : Bhi;
        int ka = c & (nc - 1);
        const bf16* Bg = Bb + (size_t)bn * ldb + ka * 64;
        const uint32_t bOff = sbase + st * STAGE_BYTES + 16384;
        #pragma unroll
        for (int i = 0; i < 2; i++)
            CP_ASYNC16(bOff + SWZ((lr + i * 32) * 128 + lc * 16),
                       Bg + (size_t)(lr + i * 32) * ldb + lc * 8);
        CP_COMMIT();
    };
    // A+B cp.async (bf16 mode)
    auto issueAB = [&](int c, int st) {
        const bf16 *Ab, *Bb;
        if (c < nc)          { Ab = Ahi; Bb = Bhi; }
        else if (c < 2 * nc) { Ab = Ahi; Bb = Blo; }
        else                 { Ab = Alo; Bb = Bhi; }
        int ka = c & (nc - 1);
        const bf16* Ag = Ab + (size_t)bm * lda + ka * 64;
        const bf16* Bg = Bb + (size_t)bn * ldb + ka * 64;
        const uint32_t aOff = sbase + st * STAGE_BYTES;
        const uint32_t bOff = aOff + 16384;
        #pragma unroll
        for (int i = 0; i < 4; i++)
            CP_ASYNC16(aOff + SWZ((lr + i * 32) * 128 + lc * 16),
                       Ag + (size_t)(lr + i * 32) * lda + lc * 8);
        #pragma unroll
        for (int i = 0; i < 2; i++)
            CP_ASYNC16(bOff + SWZ((lr + i * 32) * 128 + lc * 16),
                       Bg + (size_t)(lr + i * 32) * ldb + lc * 8);
        CP_COMMIT();
    };

    if (AFP32) { ldgcvtA(0, u); issueB(0, 0); }
    else       { issueAB(0, 0); }

    for (int c = 0; c < nch; c++) {
        if (AFP32) stsA(u, c & 1);
        if (c + 1 < nch) {
            if (AFP32) { issueB(c + 1, (c + 1) & 1); ldgcvtA(c + 1, u2); }
            else       { issueAB(c + 1, (c + 1) & 1); }
            CP_WAIT1();
        } else {
            CP_WAIT0();
        }
        __syncthreads();

        const uint32_t sA = sbase + (c & 1) * STAGE_BYTES;
        const uint32_t sB = sA + 16384;
        #pragma unroll
        for (int k16 = 0; k16 < 4; k16++) {
            const int kb = k16 * 32;
            uint32_t af[2][4], bfr[2][4];
            #pragma unroll
            for (int mt = 0; mt < 2; mt++) {
                int row = m_base + mt * 16 + ((phase & 1) << 3) + r_in;
                int col = kb + ((phase >> 1) << 4);
                LDSM_X4(af[mt][0], af[mt][1], af[mt][2], af[mt][3],
                        sA + SWZ(row * 128 + col));
            }
            #pragma unroll
            for (int ng = 0; ng < 2; ng++) {
                int row = n_base + ng * 16 + ((phase >> 1) << 3) + r_in;
                int col = kb + ((phase & 1) << 4);
                LDSM_X4(bfr[ng][0], bfr[ng][1], bfr[ng][2], bfr[ng][3],
                        sB + SWZ(row * 128 + col));
            }
            #pragma unroll
            for (int mt = 0; mt < 2; mt++)
                #pragma unroll
                for (int ng = 0; ng < 2; ng++) {
                    MMA16816(acc[mt][ng * 2 + 0],
                             af[mt][0], af[mt][1], af[mt][2], af[mt][3],
                             bfr[ng][0], bfr[ng][1]);
                    MMA16816(acc[mt][ng * 2 + 1],
                             af[mt][0], af[mt][1], af[mt][2], af[mt][3],
                             bfr[ng][2], bfr[ng][3]);
                }
        }
        __syncthreads();

        if (AFP32 && c + 1 < nch) {
            #pragma unroll
            for (int j = 0; j < 4; j++) u[j] = u2[j];
        }
    }

    // Epilogue
    const int g = lid >> 2, t2 = (lid & 3) * 2;
    #pragma unroll
    for (int mt = 0; mt < 2; mt++) {
        const int m0r = bm + m_base + mt * 16 + g;
        #pragma unroll
        for (int nt = 0; nt < 4; nt++) {
            const int n = bn + n_base + nt * 8 + t2;
            float b0v = (n < N_out)     ? bias[n]     : 0.f;
            float b1v = (n + 1 < N_out) ? bias[n + 1] : 0.f;
            float v0 = acc[mt][nt][0] + b0v, v1 = acc[mt][nt][1] + b1v;
            float v2 = acc[mt][nt][2] + b0v, v3 = acc[mt][nt][3] + b1v;
            if (RELU) {
                v0 = fmaxf(v0, 0.f); v1 = fmaxf(v1, 0.f);
                v2 = fmaxf(v2, 0.f); v3 = fmaxf(v3, 0.f);
            }
            if (SPLIT) {
                bf16 h0, l0, h1, l1;
                split2(v0, h0, l0); split2(v1, h1, l1);
                __nv_bfloat162 ph; ph.x = h0; ph.y = h1;
                __nv_bfloat162 pl; pl.x = l0; pl.y = l1;
                *reinterpret_cast<__nv_bfloat162*>(Chi + (size_t)m0r * ldc + n) = ph;
                *reinterpret_cast<__nv_bfloat162*>(Clo + (size_t)m0r * ldc + n) = pl;
                split2(v2, h0, l0); split2(v3, h1, l1);
                ph.x = h0; ph.y = h1; pl.x = l0; pl.y = l1;
                *reinterpret_cast<__nv_bfloat162*>(Chi + (size_t)(m0r + 8) * ldc + n) = ph;
                *reinterpret_cast<__nv_bfloat162*>(Clo + (size_t)(m0r + 8) * ldc + n) = pl;
            } else if (n < N_out) {
                *reinterpret_cast<float2*>(Cf + (size_t)m0r * ldc + n)       = make_float2(v0, v1);
                *reinterpret_cast<float2*>(Cf + (size_t)(m0r + 8) * ldc + n) = make_float2(v2, v3);
            }
        }
    }
}

// ---------------------------------------------------------------------------
// Prep: 4 weight splits + Gram + change reset. 513 blocks.
// ---------------------------------------------------------------------------
__device__ __forceinline__ void wsplit_blk(const float* __restrict__ W,
                                           bf16* __restrict__ Bhi, bf16* __restrict__ Blo,
                                           int K, int N, int K_pad, int blk)
{
    int idx = blk * 256 + threadIdx.x;
    int n = idx / K_pad, k = idx % K_pad;
    float v = (n < N && k < K) ? W[(size_t)k * N + n] : 0.f;
    bf16 h, l; split2(v, h, l);
    Bhi[idx] = h; Blo[idx] = l;
}

__global__ void prep_kernel(const float* __restrict__ w1, const float* __restrict__ w2,
                            const float* __restrict__ w3, const float* __restrict__ w4,
                            const float* __restrict__ attr)
{
    int b = blockIdx.x;
    if (b < 128) {
        wsplit_blk(w1, g_W1hi, g_W1lo, 100, 256, 128, b);
    } else if (b < 256) {
        wsplit_blk(w2, g_W2hi, g_W2lo, 256, 128, 256, b - 128);
    } else if (b < 384) {
        wsplit_blk(w3, g_W3hi, g_W3lo, 128, 256, 128, b - 256);
    } else if (b < 512) {
        wsplit_blk(w4, g_W4hi, g_W4lo, 256, 100, 256, b - 384);
    } else {
        int i = threadIdx.x;
        if (i == 0) g_change = 0.f;
        if (i < N_ATT * N_ATT) {
            int a = i / N_ATT, bb = i % N_ATT;
            float s = 0.f;
            for (int d = 0; d < D_DIM; d++)
                s += attr[a * D_DIM + d] * attr[bb * D_DIM + d];
            g_Gram[i] = s;
        }
    }
}

// ---------------------------------------------------------------------------
// Attractor dynamics (R4 best-measured config, fp32 output only): one thread
// per token, rsqrtf per iteration, scalar Gram reads, 49 dual-space iters +
// explicit fp32 50th step reproducing the reference's quantized "change".
// ---------------------------------------------------------------------------
__global__ __launch_bounds__(128)
void attractor_kernel(const float* __restrict__ emb,
                      const float* __restrict__ attr,
                      float* __restrict__ out_field)
{
    __shared__ float4 sA[N_ATT][32];
    __shared__ float  sG[N_ATT * N_ATT];
    __shared__ float  red[4];

    const int tid = threadIdx.x;
    for (int i = tid; i < N_ATT * 32; i += blockDim.x) {
        int a = i / 32, c = i % 32;
        sA[a][c] = reinterpret_cast<const float4*>(attr)[a * 32 + c];
    }
    for (int i = tid; i < N_ATT * N_ATT; i += blockDim.x) sG[i] = g_Gram[i];
    __syncthreads();

    const int tok = blockIdx.x * blockDim.x + tid;
    const float4* e4 = reinterpret_cast<const float4*>(emb + (size_t)tok * D_DIM);

    float g[N_ATT];
    #pragma unroll
    for (int a = 0; a < N_ATT; a++) g[a] = 0.f;
    float q = 0.f;
    #pragma unroll 4
    for (int c = 0; c < 32; c++) {
        float4 e = e4[c];
        q += e.x*e.x + e.y*e.y + e.z*e.z + e.w*e.w;
        #pragma unroll
        for (int a = 0; a < N_ATT; a++) {
            float4 av = sA[a][c];
            g[a] += e.x*av.x + e.y*av.y + e.z*av.z + e.w*av.w;
        }
    }

    float W[N_ATT];
    #pragma unroll
    for (int a = 0; a < N_ATT; a++) W[a] = 0.f;
    float Atot = 1.f;
    const float SG = STEPSZ * GRAV;

    #pragma unroll 1
    for (int t = 0; t < N_ITERS - 1; t++) {
        float s[N_ATT], S = 0.f;
        #pragma unroll
        for (int a = 0; a < N_ATT; a++) {
            float d2 = sG[a * N_ATT + a] - 2.f * g[a] + q;
            float r  = rsqrtf(d2);
            float ss = SG * r * r * r;
            s[a] = ss; S += ss;
        }
        float alpha = 1.f - S;
        float v[N_ATT], sv = 0.f, sg = 0.f;
        #pragma unroll
        for (int a = 0; a < N_ATT; a++) {
            float va = 0.f;
            #pragma unroll
            for (int b = 0; b < N_ATT; b++) va += s[b] * sG[a * N_ATT + b];
            v[a] = va; sv += s[a] * va; sg += s[a] * g[a];
        }
        q = alpha * alpha * q + 2.f * alpha * sg + sv;
        #pragma unroll
        for (int a = 0; a < N_ATT; a++) {
            g[a] = alpha * g[a] + v[a];
            W[a] = alpha * W[a] + s[a];
        }
        Atot *= alpha;
    }

    float s[N_ATT], S = 0.f;
    #pragma unroll
    for (int a = 0; a < N_ATT; a++) {
        float d2 = sG[a * N_ATT + a] - 2.f * g[a] + q;
        float r  = rsqrtf(d2);
        float ss = SG * r * r * r;
        s[a] = ss; S += ss;
    }

    float chg2 = 0.f;
    float4* o4 = reinterpret_cast<float4*>(out_field + (size_t)tok * D_DIM);
    #pragma unroll 4
    for (int c = 0; c < 32; c++) {
        float4 e = e4[c];
        float px = Atot*e.x, py = Atot*e.y, pz = Atot*e.z, pw = Atot*e.w;
        float fx = 0.f, fy = 0.f, fz = 0.f, fw = 0.f;
        #pragma unroll
        for (int a = 0; a < N_ATT; a++) {
            float4 av = sA[a][c];
            px += W[a]*av.x; py += W[a]*av.y; pz += W[a]*av.z; pw += W[a]*av.w;
            fx += s[a]*av.x; fy += s[a]*av.y; fz += s[a]*av.z; fw += s[a]*av.w;
        }
        float nx = px + (fx - S*px);
        float ny = py + (fy - S*py);
        float nz = pz + (fz - S*pz);
        float nw = pw + (fw - S*pw);
        float dx = nx-px, dy = ny-py, dz = nz-pz, dw = nw-pw;
        chg2 += dx*dx + dy*dy + dz*dz + dw*dw;
        o4[c] = make_float4(nx, ny, nz, nw);
    }

    #pragma unroll
    for (int sft = 16; sft > 0; sft >>= 1)
        chg2 += __shfl_xor_sync(0xFFFFFFFFu, chg2, sft);
    if ((tid & 31) == 0) red[tid >> 5] = chg2;
    __syncthreads();
    if (tid == 0) atomicAdd(&g_change, red[0] + red[1] + red[2] + red[3]);
}

__global__ void finish_kernel(float* __restrict__ out)
{
    out[0] = sqrtf(g_change);
}

// ---------------------------------------------------------------------------
extern "C" void kernel_launch(void* const* d_in, const int* in_sizes, int n_in,
                              void* d_out, int out_size)
{
    const float* text   = (const float*)d_in[0];
    const float* enc_w1 = (const float*)d_in[1];
    const float* enc_b1 = (const float*)d_in[2];
    const float* enc_w2 = (const float*)d_in[3];
    const float* enc_b2 = (const float*)d_in[4];
    const float* attr   = (const float*)d_in[5];
    const float* dec_w1 = (const float*)d_in[6];
    const float* dec_b1 = (const float*)d_in[7];
    const float* dec_w2 = (const float*)d_in[8];
    const float* dec_b2 = (const float*)d_in[9];

    float* out       = (float*)d_out;
    float* out_field = out;
    float* out_rec   = out + OUT_FIELD_ELEMS;
    float* out_chg   = out + OUT_FIELD_ELEMS + OUT_REC_ELEMS;

    bf16 *Hhi, *Hlo;
    bf16 *W1hi, *W1lo, *W2hi, *W2lo, *W3hi, *W3lo, *W4hi, *W4lo;
    float* EMB;
    cudaGetSymbolAddress((void**)&Hhi,  g_Hhi);  cudaGetSymbolAddress((void**)&Hlo,  g_Hlo);
    cudaGetSymbolAddress((void**)&W1hi, g_W1hi); cudaGetSymbolAddress((void**)&W1lo, g_W1lo);
    cudaGetSymbolAddress((void**)&W2hi, g_W2hi); cudaGetSymbolAddress((void**)&W2lo, g_W2lo);
    cudaGetSymbolAddress((void**)&W3hi, g_W3hi); cudaGetSymbolAddress((void**)&W3lo, g_W3lo);
    cudaGetSymbolAddress((void**)&W4hi, g_W4hi); cudaGetSymbolAddress((void**)&W4lo, g_W4lo);
    cudaGetSymbolAddress((void**)&EMB,  g_EMB);

    // Prep (weight splits + Gram + reset)
    prep_kernel<<<513, 256>>>(enc_w1, enc_w2, dec_w1, dec_w2, attr);

    // enc1: fp32-A (text, Kact=100, lda=100) @ W1 -> relu -> H hi/lo, N=256
    mma_gemm<true, true, true><<<dim3(M_TOK / 128, 4), 256>>>(
        text, 100, nullptr, nullptr, 100,
        W1hi, W1lo, 128, enc_b1,
        nullptr, Hhi, Hlo, 256, 256, 2);
    // enc2: bf16-A (H hi/lo) @ W2 -> EMB fp32, N=128
    mma_gemm<false, false, false><<<dim3(M_TOK / 128, 2), 256>>>(
        nullptr, 0, Hhi, Hlo, 256,
        W2hi, W2lo, 256, enc_b2,
        EMB, nullptr, nullptr, 128, 128, 4);

    // Attractor: fp32 field only (R4 epilogue)
    attractor_kernel<<<M_TOK / 128, 128>>>(EMB, attr, out_field);

    // dec1: fp32-A (field, Kact=128, lda=128) @ W3 -> relu -> H hi/lo, N=256
    mma_gemm<true, true, true><<<dim3(M_TOK / 128, 4), 256>>>(
        out_field, 128, nullptr, nullptr, 128,
        W3hi, W3lo, 128, dec_b1,
        nullptr, Hhi, Hlo, 256, 256, 2);
    // dec2: bf16-A (H hi/lo) @ W4 -> out_rec fp32, N=100 (ldc=100)
    mma_gemm<false, false, false><<<dim3(M_TOK / 128, 2), 256>>>(
        nullptr, 0, Hhi, Hlo, 256,
        W4hi, W4lo, 256, dec_b2,
        out_rec, nullptr, nullptr, 100, 100, 4);

    finish_kernel<<<1, 1>>>(out_chg);
}

// round 12
// speedup vs baseline: 1.2277x; 1.2277x over previous
#include <cuda_runtime.h>
#include <cuda_bf16.h>
#include <cstdint>

typedef __nv_bfloat16 bf16;

#define M_TOK   32768
#define D_DIM   128
#define N_ATT   10
#define GRAV    0.001f
#define STEPSZ  0.01f
#define N_ITERS 50

#define OUT_FIELD_ELEMS (M_TOK * 128)
#define OUT_REC_ELEMS   (M_TOK * 100)

// ---------------- device scratch (allocation-free rule) --------------------
__device__ bf16  g_Thi[M_TOK * 128], g_Tlo[M_TOK * 128];   // text, K padded 100->128
__device__ bf16  g_Hhi[M_TOK * 256], g_Hlo[M_TOK * 256];   // hidden (enc1/dec1 out)
__device__ bf16  g_Fhi[M_TOK * 128], g_Flo[M_TOK * 128];   // attractor field split
__device__ float g_EMB[M_TOK * 128];                       // enc2 out (fp32)
__device__ bf16  g_W1hi[256 * 128], g_W1lo[256 * 128];     // [N,Kpad] K-major
__device__ bf16  g_W2hi[128 * 256], g_W2lo[128 * 256];
__device__ bf16  g_W3hi[256 * 128], g_W3lo[256 * 128];
__device__ bf16  g_W4hi[128 * 256], g_W4lo[128 * 256];     // N 100->128 padded
__device__ float g_Gram[N_ATT * N_ATT];
__device__ float g_change;

// ---------------- helpers ---------------------------------------------------
__device__ __forceinline__ uint32_t smem_u32(const void* p) {
    uint32_t a;
    asm("{ .reg .u64 t; cvta.to.shared.u64 t, %1; cvt.u32.u64 %0, t; }" : "=r"(a) : "l"(p));
    return a;
}
#define SWZ(off) ((off) ^ (((off) >> 3) & 0x70))

#define CP_ASYNC16(dst, src) \
    asm volatile("cp.async.ca.shared.global [%0], [%1], 16;" :: "r"(dst), "l"(src))
#define CP_COMMIT() asm volatile("cp.async.commit_group;" ::: "memory")
#define CP_WAIT1()  asm volatile("cp.async.wait_group 1;" ::: "memory")
#define CP_WAIT0()  asm volatile("cp.async.wait_group 0;" ::: "memory")

#define LDSM_X4(r0, r1, r2, r3, addr) \
    asm volatile("ldmatrix.sync.aligned.m8n8.x4.shared.b16 {%0,%1,%2,%3}, [%4];" \
        : "=r"(r0), "=r"(r1), "=r"(r2), "=r"(r3) : "r"(addr))

#define MMA16816(d, a0, a1, a2, a3, b0, b1) \
    asm volatile("mma.sync.aligned.m16n8k16.row.col.f32.bf16.bf16.f32 " \
        "{%0,%1,%2,%3}, {%4,%5,%6,%7}, {%8,%9}, {%0,%1,%2,%3};" \
        : "+f"((d)[0]), "+f"((d)[1]), "+f"((d)[2]), "+f"((d)[3]) \
        : "r"(a0), "r"(a1), "r"(a2), "r"(a3), "r"(b0), "r"(b1))

__device__ __forceinline__ void split2(float v, bf16& hi, bf16& lo) {
    hi = __float2bfloat16(v);
    lo = __float2bfloat16(v - __bfloat162float(hi));
}

// pack hi/lo bf16x2 words for a float pair (split2-compatible rounding)
__device__ __forceinline__ void split_pack2(float a, float b,
                                            uint32_t& hw, uint32_t& lw) {
    bf16 ha, la, hb, lb;
    split2(a, ha, la); split2(b, hb, lb);
    __nv_bfloat162 hp; hp.x = ha; hp.y = hb;
    __nv_bfloat162 lp; lp.x = la; lp.y = lb;
    hw = *reinterpret_cast<uint32_t*>(&hp);
    lw = *reinterpret_cast<uint32_t*>(&lp);
}

// ---------------------------------------------------------------------------
// bf16x3-split tensor-core GEMM, cp.async double-buffered (proven R7 path).
// CTA: 256 threads = 8 warps (4M x 2N), warp tile 32x32, CTA tile 128x64.
// Augmented K chunks of 64: [hi*hi | hi*lo | lo*hi], fp32 accumulation.
// ---------------------------------------------------------------------------
#define STAGE_BYTES 24576   // 16K A + 8K B, 1024-aligned

template<bool RELU, bool SPLIT>
__global__ __launch_bounds__(256)
void mma_gemm(const bf16* __restrict__ Ahi, const bf16* __restrict__ Alo, int lda,
              const bf16* __restrict__ Bhi, const bf16* __restrict__ Blo, int ldb,
              const float* __restrict__ bias,
              float* __restrict__ Cf, bf16* __restrict__ Chi, bf16* __restrict__ Clo,
              int ldc, int N_out, int nc)
{
    __shared__ alignas(1024) char smem[2 * STAGE_BYTES];
    const uint32_t sbase = smem_u32(smem);

    const int tid = threadIdx.x;
    const int wid = tid >> 5, lid = tid & 31;
    const int bm = blockIdx.x * 128, bn = blockIdx.y * 64;
    const int warpM = wid >> 1, warpN = wid & 1;
    const int m_base = warpM * 32, n_base = warpN * 32;
    const int phase = lid >> 3, r_in = lid & 7;
    const int lr = tid >> 3, lc = tid & 7;

    const int nch = 3 * nc;

    float acc[2][4][4];
    #pragma unroll
    for (int mt = 0; mt < 2; mt++)
        #pragma unroll
        for (int nt = 0; nt < 4; nt++)
            #pragma unroll
            for (int e = 0; e < 4; e++) acc[mt][nt][e] = 0.f;

    auto issue = [&](int c, int st) {
        const bf16 *Ab, *Bb; int ka;
        if (c < nc)          { Ab = Ahi; Bb = Bhi; ka = c; }
        else if (c < 2 * nc) { Ab = Ahi; Bb = Blo; ka = c - nc; }
        else                 { Ab = Alo; Bb = Bhi; ka = c - 2 * nc; }
        const bf16* Ag = Ab + (size_t)bm * lda + ka * 64;
        const bf16* Bg = Bb + (size_t)bn * ldb + ka * 64;
        const uint32_t aOff = sbase + st * STAGE_BYTES;
        const uint32_t bOff = aOff + 16384;
        #pragma unroll
        for (int i = 0; i < 4; i++)
            CP_ASYNC16(aOff + SWZ((lr + i * 32) * 128 + lc * 16),
                       Ag + (size_t)(lr + i * 32) * lda + lc * 8);
        #pragma unroll
        for (int i = 0; i < 2; i++)
            CP_ASYNC16(bOff + SWZ((lr + i * 32) * 128 + lc * 16),
                       Bg + (size_t)(lr + i * 32) * ldb + lc * 8);
        CP_COMMIT();
    };

    issue(0, 0);

    for (int c = 0; c < nch; c++) {
        if (c + 1 < nch) { issue(c + 1, (c + 1) & 1); CP_WAIT1(); }
        else             { CP_WAIT0(); }
        __syncthreads();

        const uint32_t sA = sbase + (c & 1) * STAGE_BYTES;
        const uint32_t sB = sA + 16384;
        #pragma unroll
        for (int k16 = 0; k16 < 4; k16++) {
            const int kb = k16 * 32;
            uint32_t af[2][4], bfr[2][4];
            #pragma unroll
            for (int mt = 0; mt < 2; mt++) {
                int row = m_base + mt * 16 + ((phase & 1) << 3) + r_in;
                int col = kb + ((phase >> 1) << 4);
                LDSM_X4(af[mt][0], af[mt][1], af[mt][2], af[mt][3],
                        sA + SWZ(row * 128 + col));
            }
            #pragma unroll
            for (int ng = 0; ng < 2; ng++) {
                int row = n_base + ng * 16 + ((phase >> 1) << 3) + r_in;
                int col = kb + ((phase & 1) << 4);
                LDSM_X4(bfr[ng][0], bfr[ng][1], bfr[ng][2], bfr[ng][3],
                        sB + SWZ(row * 128 + col));
            }
            #pragma unroll
            for (int mt = 0; mt < 2; mt++)
                #pragma unroll
                for (int ng = 0; ng < 2; ng++) {
                    MMA16816(acc[mt][ng * 2 + 0],
                             af[mt][0], af[mt][1], af[mt][2], af[mt][3],
                             bfr[ng][0], bfr[ng][1]);
                    MMA16816(acc[mt][ng * 2 + 1],
                             af[mt][0], af[mt][1], af[mt][2], af[mt][3],
                             bfr[ng][2], bfr[ng][3]);
                }
        }
        __syncthreads();
    }

    // Epilogue
    const int g = lid >> 2, t2 = (lid & 3) * 2;
    #pragma unroll
    for (int mt = 0; mt < 2; mt++) {
        const int m0r = bm + m_base + mt * 16 + g;
        #pragma unroll
        for (int nt = 0; nt < 4; nt++) {
            const int n = bn + n_base + nt * 8 + t2;
            float b0v = (n < N_out)     ? bias[n]     : 0.f;
            float b1v = (n + 1 < N_out) ? bias[n + 1] : 0.f;
            float v0 = acc[mt][nt][0] + b0v, v1 = acc[mt][nt][1] + b1v;
            float v2 = acc[mt][nt][2] + b0v, v3 = acc[mt][nt][3] + b1v;
            if (RELU) {
                v0 = fmaxf(v0, 0.f); v1 = fmaxf(v1, 0.f);
                v2 = fmaxf(v2, 0.f); v3 = fmaxf(v3, 0.f);
            }
            if (SPLIT) {
                uint32_t hw, lw;
                split_pack2(v0, v1, hw, lw);
                *reinterpret_cast<uint32_t*>(Chi + (size_t)m0r * ldc + n) = hw;
                *reinterpret_cast<uint32_t*>(Clo + (size_t)m0r * ldc + n) = lw;
                split_pack2(v2, v3, hw, lw);
                *reinterpret_cast<uint32_t*>(Chi + (size_t)(m0r + 8) * ldc + n) = hw;
                *reinterpret_cast<uint32_t*>(Clo + (size_t)(m0r + 8) * ldc + n) = lw;
            } else if (n < N_out) {
                *reinterpret_cast<float2*>(Cf + (size_t)m0r * ldc + n)       = make_float2(v0, v1);
                *reinterpret_cast<float2*>(Cf + (size_t)(m0r + 8) * ldc + n) = make_float2(v2, v3);
            }
        }
    }
}

// ---------------------------------------------------------------------------
// Fused prep: text split + 4 weight splits + Gram + change reset. One launch.
// ---------------------------------------------------------------------------
__device__ __forceinline__ void wsplit_blk(const float* __restrict__ W,
                                           bf16* __restrict__ Bhi, bf16* __restrict__ Blo,
                                           int K, int N, int K_pad, int blk)
{
    int idx = blk * 256 + threadIdx.x;
    int n = idx / K_pad, k = idx % K_pad;
    float v = (n < N && k < K) ? W[(size_t)k * N + n] : 0.f;
    bf16 h, l; split2(v, h, l);
    Bhi[idx] = h; Blo[idx] = l;
}

__global__ void prep_kernel(const float* __restrict__ text,
                            const float* __restrict__ w1, const float* __restrict__ w2,
                            const float* __restrict__ w3, const float* __restrict__ w4,
                            const float* __restrict__ attr)
{
    int b = blockIdx.x;
    if (b < 16384) {
        int idx = b * 256 + threadIdx.x;          // M_TOK*128
        int m = idx >> 7, k = idx & 127;
        float v = (k < 100) ? text[(size_t)m * 100 + k] : 0.f;
        bf16 h, l; split2(v, h, l);
        g_Thi[idx] = h; g_Tlo[idx] = l;
    } else if (b < 16512) {
        wsplit_blk(w1, g_W1hi, g_W1lo, 100, 256, 128, b - 16384);
    } else if (b < 16640) {
        wsplit_blk(w2, g_W2hi, g_W2lo, 256, 128, 256, b - 16512);
    } else if (b < 16768) {
        wsplit_blk(w3, g_W3hi, g_W3lo, 128, 256, 128, b - 16640);
    } else if (b < 16896) {
        wsplit_blk(w4, g_W4hi, g_W4lo, 256, 100, 256, b - 16768);
    } else {
        int i = threadIdx.x;
        if (i == 0) g_change = 0.f;
        if (i < N_ATT * N_ATT) {
            int a = i / N_ATT, bb = i % N_ATT;
            float s = 0.f;
            for (int d = 0; d < D_DIM; d++)
                s += attr[a * D_DIM + d] * attr[bb * D_DIM + d];
            g_Gram[i] = s;
        }
    }
}

// ---------------------------------------------------------------------------
// Attractor dynamics (R4 body): one thread per token, rsqrtf per iteration,
// scalar Gram reads, 49 dual-space iters + explicit fp32 50th step. The
// bf16 hi/lo field split is buffered in registers and stored as uint4
// (16 stores per array instead of 64 scattered 4B stores).
// ---------------------------------------------------------------------------
__global__ __launch_bounds__(128)
void attractor_kernel(const float* __restrict__ emb,
                      const float* __restrict__ attr,
                      float* __restrict__ out_field)
{
    __shared__ float4 sA[N_ATT][32];
    __shared__ float  sG[N_ATT * N_ATT];
    __shared__ float  red[4];

    const int tid = threadIdx.x;
    for (int i = tid; i < N_ATT * 32; i += blockDim.x) {
        int a = i / 32, c = i % 32;
        sA[a][c] = reinterpret_cast<const float4*>(attr)[a * 32 + c];
    }
    for (int i = tid; i < N_ATT * N_ATT; i += blockDim.x) sG[i] = g_Gram[i];
    __syncthreads();

    const int tok = blockIdx.x * blockDim.x + tid;
    const float4* e4 = reinterpret_cast<const float4*>(emb + (size_t)tok * D_DIM);

    float g[N_ATT];
    #pragma unroll
    for (int a = 0; a < N_ATT; a++) g[a] = 0.f;
    float q = 0.f;
    #pragma unroll 4
    for (int c = 0; c < 32; c++) {
        float4 e = e4[c];
        q += e.x*e.x + e.y*e.y + e.z*e.z + e.w*e.w;
        #pragma unroll
        for (int a = 0; a < N_ATT; a++) {
            float4 av = sA[a][c];
            g[a] += e.x*av.x + e.y*av.y + e.z*av.z + e.w*av.w;
        }
    }

    float W[N_ATT];
    #pragma unroll
    for (int a = 0; a < N_ATT; a++) W[a] = 0.f;
    float Atot = 1.f;
    const float SG = STEPSZ * GRAV;

    #pragma unroll 1
    for (int t = 0; t < N_ITERS - 1; t++) {
        float s[N_ATT], S = 0.f;
        #pragma unroll
        for (int a = 0; a < N_ATT; a++) {
            float d2 = sG[a * N_ATT + a] - 2.f * g[a] + q;
            float r  = rsqrtf(d2);
            float ss = SG * r * r * r;
            s[a] = ss; S += ss;
        }
        float alpha = 1.f - S;
        float v[N_ATT], sv = 0.f, sg = 0.f;
        #pragma unroll
        for (int a = 0; a < N_ATT; a++) {
            float va = 0.f;
            #pragma unroll
            for (int b = 0; b < N_ATT; b++) va += s[b] * sG[a * N_ATT + b];
            v[a] = va; sv += s[a] * va; sg += s[a] * g[a];
        }
        q = alpha * alpha * q + 2.f * alpha * sg + sv;
        #pragma unroll
        for (int a = 0; a < N_ATT; a++) {
            g[a] = alpha * g[a] + v[a];
            W[a] = alpha * W[a] + s[a];
        }
        Atot *= alpha;
    }

    float s[N_ATT], S = 0.f;
    #pragma unroll
    for (int a = 0; a < N_ATT; a++) {
        float d2 = sG[a * N_ATT + a] - 2.f * g[a] + q;
        float r  = rsqrtf(d2);
        float ss = SG * r * r * r;
        s[a] = ss; S += ss;
    }

    float chg2 = 0.f;
    float4* o4 = reinterpret_cast<float4*>(out_field + (size_t)tok * D_DIM);
    uint4* fh4 = reinterpret_cast<uint4*>(g_Fhi + (size_t)tok * D_DIM);
    uint4* fl4 = reinterpret_cast<uint4*>(g_Flo + (size_t)tok * D_DIM);

    // Process 32 float4 groups in 4 batches of 8; pack hi/lo into uint4s.
    #pragma unroll
    for (int batch = 0; batch < 4; batch++) {
        uint32_t hbuf[16], lbuf[16];
        #pragma unroll
        for (int j = 0; j < 8; j++) {
            const int c = batch * 8 + j;
            float4 e = e4[c];
            float px = Atot*e.x, py = Atot*e.y, pz = Atot*e.z, pw = Atot*e.w;
            float fx = 0.f, fy = 0.f, fz = 0.f, fw = 0.f;
            #pragma unroll
            for (int a = 0; a < N_ATT; a++) {
                float4 av = sA[a][c];
                px += W[a]*av.x; py += W[a]*av.y; pz += W[a]*av.z; pw += W[a]*av.w;
                fx += s[a]*av.x; fy += s[a]*av.y; fz += s[a]*av.z; fw += s[a]*av.w;
            }
            float nx = px + (fx - S*px);
            float ny = py + (fy - S*py);
            float nz = pz + (fz - S*pz);
            float nw = pw + (fw - S*pw);
            float dx = nx-px, dy = ny-py, dz = nz-pz, dw = nw-pw;
            chg2 += dx*dx + dy*dy + dz*dz + dw*dw;
            o4[c] = make_float4(nx, ny, nz, nw);
            split_pack2(nx, ny, hbuf[j*2],   lbuf[j*2]);
            split_pack2(nz, nw, hbuf[j*2+1], lbuf[j*2+1]);
        }
        #pragma unroll
        for (int j = 0; j < 4; j++) {
            fh4[batch * 4 + j] = make_uint4(hbuf[j*4], hbuf[j*4+1], hbuf[j*4+2], hbuf[j*4+3]);
            fl4[batch * 4 + j] = make_uint4(lbuf[j*4], lbuf[j*4+1], lbuf[j*4+2], lbuf[j*4+3]);
        }
    }

    #pragma unroll
    for (int sft = 16; sft > 0; sft >>= 1)
        chg2 += __shfl_xor_sync(0xFFFFFFFFu, chg2, sft);
    if ((tid & 31) == 0) red[tid >> 5] = chg2;
    __syncthreads();
    if (tid == 0) atomicAdd(&g_change, red[0] + red[1] + red[2] + red[3]);
}

__global__ void finish_kernel(float* __restrict__ out)
{
    out[0] = sqrtf(g_change);
}

// ---------------------------------------------------------------------------
extern "C" void kernel_launch(void* const* d_in, const int* in_sizes, int n_in,
                              void* d_out, int out_size)
{
    const float* text   = (const float*)d_in[0];
    const float* enc_w1 = (const float*)d_in[1];
    const float* enc_b1 = (const float*)d_in[2];
    const float* enc_w2 = (const float*)d_in[3];
    const float* enc_b2 = (const float*)d_in[4];
    const float* attr   = (const float*)d_in[5];
    const float* dec_w1 = (const float*)d_in[6];
    const float* dec_b1 = (const float*)d_in[7];
    const float* dec_w2 = (const float*)d_in[8];
    const float* dec_b2 = (const float*)d_in[9];

    float* out       = (float*)d_out;
    float* out_field = out;
    float* out_rec   = out + OUT_FIELD_ELEMS;
    float* out_chg   = out + OUT_FIELD_ELEMS + OUT_REC_ELEMS;

    bf16 *Thi, *Tlo, *Hhi, *Hlo, *Fhi, *Flo;
    bf16 *W1hi, *W1lo, *W2hi, *W2lo, *W3hi, *W3lo, *W4hi, *W4lo;
    float* EMB;
    cudaGetSymbolAddress((void**)&Thi,  g_Thi);  cudaGetSymbolAddress((void**)&Tlo,  g_Tlo);
    cudaGetSymbolAddress((void**)&Hhi,  g_Hhi);  cudaGetSymbolAddress((void**)&Hlo,  g_Hlo);
    cudaGetSymbolAddress((void**)&Fhi,  g_Fhi);  cudaGetSymbolAddress((void**)&Flo,  g_Flo);
    cudaGetSymbolAddress((void**)&W1hi, g_W1hi); cudaGetSymbolAddress((void**)&W1lo, g_W1lo);
    cudaGetSymbolAddress((void**)&W2hi, g_W2hi); cudaGetSymbolAddress((void**)&W2lo, g_W2lo);
    cudaGetSymbolAddress((void**)&W3hi, g_W3hi); cudaGetSymbolAddress((void**)&W3lo, g_W3lo);
    cudaGetSymbolAddress((void**)&W4hi, g_W4hi); cudaGetSymbolAddress((void**)&W4lo, g_W4lo);
    cudaGetSymbolAddress((void**)&EMB,  g_EMB);

    // Fused prep (text+weights split, Gram, reset) — one launch
    prep_kernel<<<16897, 256>>>(text, enc_w1, enc_w2, dec_w1, dec_w2, attr);

    // enc1: [M,100p128] @ W1 -> relu -> H (bf16 split), N=256
    mma_gemm<true, true><<<dim3(M_TOK / 128, 4), 256>>>(
        Thi, Tlo, 128, W1hi, W1lo, 128, enc_b1,
        nullptr, Hhi, Hlo, 256, 256, 2);
    // enc2: [M,256] @ W2 -> EMB fp32, N=128
    mma_gemm<false, false><<<dim3(M_TOK / 128, 2), 256>>>(
        Hhi, Hlo, 256, W2hi, W2lo, 256, enc_b2,
        EMB, nullptr, nullptr, 128, 128, 4);

    // Attractor: 1 thread per token, packed uint4 split stores
    attractor_kernel<<<M_TOK / 128, 128>>>(EMB, attr, out_field);

    // dec1: [M,128] @ W3 -> relu -> H (bf16 split), N=256
    mma_gemm<true, true><<<dim3(M_TOK / 128, 4), 256>>>(
        Fhi, Flo, 128, W3hi, W3lo, 128, dec_b1,
        nullptr, Hhi, Hlo, 256, 256, 2);
    // dec2: [M,256] @ W4 -> out_rec fp32, N=100 (ldc=100)
    mma_gemm<false, false><<<dim3(M_TOK / 128, 2), 256>>>(
        Hhi, Hlo, 256, W4hi, W4lo, 256, dec_b2,
        out_rec, nullptr, nullptr, 100, 100, 4);

    finish_kernel<<<1, 1>>>(out_chg);
}

// round 14
// speedup vs baseline: 1.3042x; 1.0623x over previous
#include <cuda_runtime.h>
#include <cuda_bf16.h>
#include <cstdint>

typedef __nv_bfloat16 bf16;
typedef unsigned long long F2;   // packed fp32x2

#define M_TOK   32768
#define D_DIM   128
#define N_ATT   10
#define GRAV    0.001f
#define STEPSZ  0.01f
#define N_ITERS 50

#define OUT_FIELD_ELEMS (M_TOK * 128)
#define OUT_REC_ELEMS   (M_TOK * 100)

// ---------------- device scratch (allocation-free rule) --------------------
__device__ bf16  g_Thi[M_TOK * 128], g_Tlo[M_TOK * 128];   // text, K padded 100->128
__device__ bf16  g_Hhi[M_TOK * 256], g_Hlo[M_TOK * 256];   // hidden (enc1/dec1 out)
__device__ bf16  g_Fhi[M_TOK * 128], g_Flo[M_TOK * 128];   // attractor field split
__device__ float g_EMB[M_TOK * 128];                       // enc2 out (fp32)
__device__ bf16  g_W1hi[256 * 128], g_W1lo[256 * 128];     // [N,Kpad] K-major
__device__ bf16  g_W2hi[128 * 256], g_W2lo[128 * 256];
__device__ bf16  g_W3hi[256 * 128], g_W3lo[256 * 128];
__device__ bf16  g_W4hi[128 * 256], g_W4lo[128 * 256];     // N 100->128 padded
__device__ float g_Gram[N_ATT * N_ATT];
__device__ float g_change;
__device__ int   g_done;

// ---------------- helpers ---------------------------------------------------
__device__ __forceinline__ uint32_t smem_u32(const void* p) {
    uint32_t a;
    asm("{ .reg .u64 t; cvta.to.shared.u64 t, %1; cvt.u32.u64 %0, t; }" : "=r"(a) : "l"(p));
    return a;
}
#define SWZ(off) ((off) ^ (((off) >> 3) & 0x70))

#define CP_ASYNC16(dst, src) \
    asm volatile("cp.async.ca.shared.global [%0], [%1], 16;" :: "r"(dst), "l"(src))
#define CP_COMMIT() asm volatile("cp.async.commit_group;" ::: "memory")
#define CP_WAIT1()  asm volatile("cp.async.wait_group 1;" ::: "memory")
#define CP_WAIT0()  asm volatile("cp.async.wait_group 0;" ::: "memory")

#define LDSM_X4(r0, r1, r2, r3, addr) \
    asm volatile("ldmatrix.sync.aligned.m8n8.x4.shared.b16 {%0,%1,%2,%3}, [%4];" \
        : "=r"(r0), "=r"(r1), "=r"(r2), "=r"(r3) : "r"(addr))

#define MMA16816(d, a0, a1, a2, a3, b0, b1) \
    asm volatile("mma.sync.aligned.m16n8k16.row.col.f32.bf16.bf16.f32 " \
        "{%0,%1,%2,%3}, {%4,%5,%6,%7}, {%8,%9}, {%0,%1,%2,%3};" \
        : "+f"((d)[0]), "+f"((d)[1]), "+f"((d)[2]), "+f"((d)[3]) \
        : "r"(a0), "r"(a1), "r"(a2), "r"(a3), "r"(b0), "r"(b1))

__device__ __forceinline__ void split2(float v, bf16& hi, bf16& lo) {
    hi = __float2bfloat16(v);
    lo = __float2bfloat16(v - __bfloat162float(hi));
}

__device__ __forceinline__ void split_pack2(float a, float b,
                                            uint32_t& hw, uint32_t& lw) {
    bf16 ha, la, hb, lb;
    split2(a, ha, la); split2(b, hb, lb);
    __nv_bfloat162 hp; hp.x = ha; hp.y = hb;
    __nv_bfloat162 lp; lp.x = la; lp.y = lb;
    hw = *reinterpret_cast<uint32_t*>(&hp);
    lw = *reinterpret_cast<uint32_t*>(&lp);
}

// ---- fp32x2 packed ops (only fma.rn.f32x2, proven on this harness) --------
__device__ __forceinline__ F2 f2fma(F2 a, F2 b, F2 c) {
    F2 d; asm("fma.rn.f32x2 %0, %1, %2, %3;" : "=l"(d) : "l"(a), "l"(b), "l"(c));
    return d;
}
__device__ __forceinline__ F2 f2dup(float x) {
    F2 r; uint32_t b = __float_as_uint(x);
    asm("mov.b64 %0, {%1, %1};" : "=l"(r) : "r"(b));
    return r;
}
__device__ __forceinline__ F2 f2pack(float a, float b) {
    F2 r;
    asm("mov.b64 %0, {%1, %2};" : "=l"(r)
        : "r"(__float_as_uint(a)), "r"(__float_as_uint(b)));
    return r;
}
__device__ __forceinline__ void f2unpack(F2 v, float& a, float& b) {
    uint32_t x, y;
    asm("mov.b64 {%0, %1}, %2;" : "=r"(x), "=r"(y) : "l"(v));
    a = __uint_as_float(x); b = __uint_as_float(y);
}
__device__ __forceinline__ float f2hadd(F2 v) {
    float a, b; f2unpack(v, a, b); return a + b;
}
#define F2_ZERO 0ULL
#define F2_ONE  0x3F8000003F800000ULL

// ---------------------------------------------------------------------------
// bf16x3-split tensor-core GEMM, cp.async double-buffered (R12, unchanged).
// ---------------------------------------------------------------------------
#define STAGE_BYTES 24576

template<bool RELU, bool SPLIT>
__global__ __launch_bounds__(256)
void mma_gemm(const bf16* __restrict__ Ahi, const bf16* __restrict__ Alo, int lda,
              const bf16* __restrict__ Bhi, const bf16* __restrict__ Blo, int ldb,
              const float* __restrict__ bias,
              float* __restrict__ Cf, bf16* __restrict__ Chi, bf16* __restrict__ Clo,
              int ldc, int N_out, int nc)
{
    __shared__ alignas(1024) char smem[2 * STAGE_BYTES];
    const uint32_t sbase = smem_u32(smem);

    const int tid = threadIdx.x;
    const int wid = tid >> 5, lid = tid & 31;
    const int bm = blockIdx.x * 128, bn = blockIdx.y * 64;
    const int warpM = wid >> 1, warpN = wid & 1;
    const int m_base = warpM * 32, n_base = warpN * 32;
    const int phase = lid >> 3, r_in = lid & 7;
    const int lr = tid >> 3, lc = tid & 7;

    const int nch = 3 * nc;

    float acc[2][4][4];
    #pragma unroll
    for (int mt = 0; mt < 2; mt++)
        #pragma unroll
        for (int nt = 0; nt < 4; nt++)
            #pragma unroll
            for (int e = 0; e < 4; e++) acc[mt][nt][e] = 0.f;

    auto issue = [&](int c, int st) {
        const bf16 *Ab, *Bb; int ka;
        if (c < nc)          { Ab = Ahi; Bb = Bhi; ka = c; }
        else if (c < 2 * nc) { Ab = Ahi; Bb = Blo; ka = c - nc; }
        else                 { Ab = Alo; Bb = Bhi; ka = c - 2 * nc; }
        const bf16* Ag = Ab + (size_t)bm * lda + ka * 64;
        const bf16* Bg = Bb + (size_t)bn * ldb + ka * 64;
        const uint32_t aOff = sbase + st * STAGE_BYTES;
        const uint32_t bOff = aOff + 16384;
        #pragma unroll
        for (int i = 0; i < 4; i++)
            CP_ASYNC16(aOff + SWZ((lr + i * 32) * 128 + lc * 16),
                       Ag + (size_t)(lr + i * 32) * lda + lc * 8);
        #pragma unroll
        for (int i = 0; i < 2; i++)
            CP_ASYNC16(bOff + SWZ((lr + i * 32) * 128 + lc * 16),
                       Bg + (size_t)(lr + i * 32) * ldb + lc * 8);
        CP_COMMIT();
    };

    issue(0, 0);

    for (int c = 0; c < nch; c++) {
        if (c + 1 < nch) { issue(c + 1, (c + 1) & 1); CP_WAIT1(); }
        else             { CP_WAIT0(); }
        __syncthreads();

        const uint32_t sA = sbase + (c & 1) * STAGE_BYTES;
        const uint32_t sB = sA + 16384;
        #pragma unroll
        for (int k16 = 0; k16 < 4; k16++) {
            const int kb = k16 * 32;
            uint32_t af[2][4], bfr[2][4];
            #pragma unroll
            for (int mt = 0; mt < 2; mt++) {
                int row = m_base + mt * 16 + ((phase & 1) << 3) + r_in;
                int col = kb + ((phase >> 1) << 4);
                LDSM_X4(af[mt][0], af[mt][1], af[mt][2], af[mt][3],
                        sA + SWZ(row * 128 + col));
            }
            #pragma unroll
            for (int ng = 0; ng < 2; ng++) {
                int row = n_base + ng * 16 + ((phase >> 1) << 3) + r_in;
                int col = kb + ((phase & 1) << 4);
                LDSM_X4(bfr[ng][0], bfr[ng][1], bfr[ng][2], bfr[ng][3],
                        sB + SWZ(row * 128 + col));
            }
            #pragma unroll
            for (int mt = 0; mt < 2; mt++)
                #pragma unroll
                for (int ng = 0; ng < 2; ng++) {
                    MMA16816(acc[mt][ng * 2 + 0],
                             af[mt][0], af[mt][1], af[mt][2], af[mt][3],
                             bfr[ng][0], bfr[ng][1]);
                    MMA16816(acc[mt][ng * 2 + 1],
                             af[mt][0], af[mt][1], af[mt][2], af[mt][3],
                             bfr[ng][2], bfr[ng][3]);
                }
        }
        __syncthreads();
    }

    const int g = lid >> 2, t2 = (lid & 3) * 2;
    #pragma unroll
    for (int mt = 0; mt < 2; mt++) {
        const int m0r = bm + m_base + mt * 16 + g;
        #pragma unroll
        for (int nt = 0; nt < 4; nt++) {
            const int n = bn + n_base + nt * 8 + t2;
            float b0v = (n < N_out)     ? bias[n]     : 0.f;
            float b1v = (n + 1 < N_out) ? bias[n + 1] : 0.f;
            float v0 = acc[mt][nt][0] + b0v, v1 = acc[mt][nt][1] + b1v;
            float v2 = acc[mt][nt][2] + b0v, v3 = acc[mt][nt][3] + b1v;
            if (RELU) {
                v0 = fmaxf(v0, 0.f); v1 = fmaxf(v1, 0.f);
                v2 = fmaxf(v2, 0.f); v3 = fmaxf(v3, 0.f);
            }
            if (SPLIT) {
                uint32_t hw, lw;
                split_pack2(v0, v1, hw, lw);
                *reinterpret_cast<uint32_t*>(Chi + (size_t)m0r * ldc + n) = hw;
                *reinterpret_cast<uint32_t*>(Clo + (size_t)m0r * ldc + n) = lw;
                split_pack2(v2, v3, hw, lw);
                *reinterpret_cast<uint32_t*>(Chi + (size_t)(m0r + 8) * ldc + n) = hw;
                *reinterpret_cast<uint32_t*>(Clo + (size_t)(m0r + 8) * ldc + n) = lw;
            } else if (n < N_out) {
                *reinterpret_cast<float2*>(Cf + (size_t)m0r * ldc + n)       = make_float2(v0, v1);
                *reinterpret_cast<float2*>(Cf + (size_t)(m0r + 8) * ldc + n) = make_float2(v2, v3);
            }
        }
    }
}

// ---------------------------------------------------------------------------
// Fused prep: text split (pairs) + 4 weight splits + Gram + resets.
// ---------------------------------------------------------------------------
__device__ __forceinline__ void wsplit_blk(const float* __restrict__ W,
                                           bf16* __restrict__ Bhi, bf16* __restrict__ Blo,
                                           int K, int N, int K_pad, int blk)
{
    int idx = blk * 256 + threadIdx.x;
    int n = idx / K_pad, k = idx % K_pad;
    float v = (n < N && k < K) ? W[(size_t)k * N + n] : 0.f;
    bf16 h, l; split2(v, h, l);
    Bhi[idx] = h; Blo[idx] = l;
}

__global__ void prep_kernel(const float* __restrict__ text,
                            const float* __restrict__ w1, const float* __restrict__ w2,
                            const float* __restrict__ w3, const float* __restrict__ w4,
                            const float* __restrict__ attr)
{
    int b = blockIdx.x;
    if (b < 8192) {
        int idx = b * 256 + threadIdx.x;   // pair index over M_TOK*64
        int m = idx >> 6, kp = idx & 63;
        float2 v = make_float2(0.f, 0.f);
        if (kp < 50) v = *reinterpret_cast<const float2*>(text + (size_t)m * 100 + 2 * kp);
        uint32_t hw, lw;
        split_pack2(v.x, v.y, hw, lw);
        reinterpret_cast<uint32_t*>(g_Thi)[idx] = hw;
        reinterpret_cast<uint32_t*>(g_Tlo)[idx] = lw;
    } else if (b < 8320) {
        wsplit_blk(w1, g_W1hi, g_W1lo, 100, 256, 128, b - 8192);
    } else if (b < 8448) {
        wsplit_blk(w2, g_W2hi, g_W2lo, 256, 128, 256, b - 8320);
    } else if (b < 8576) {
        wsplit_blk(w3, g_W3hi, g_W3lo, 128, 256, 128, b - 8448);
    } else if (b < 8704) {
        wsplit_blk(w4, g_W4hi, g_W4lo, 256, 100, 256, b - 8576);
    } else {
        int i = threadIdx.x;
        if (i == 0) { g_change = 0.f; g_done = 0; }
        if (i < N_ATT * N_ATT) {
            int a = i / N_ATT, bb = i % N_ATT;
            float s = 0.f;
            for (int d = 0; d < D_DIM; d++)
                s += attr[a * D_DIM + d] * attr[bb * D_DIM + d];
            g_Gram[i] = s;
        }
    }
}

// ---------------------------------------------------------------------------
// Attractor dynamics: dual-space loop packed as fp32x2 over attractor pairs
// (5 pairs for 10 attractors); Newton-maintained rsqrt (all-fma, no MUFU in
// the loop). 49 iters + explicit fp32 50th step reproducing the reference's
// quantized "change". Recon epilogue: R12's batched uint4 split stores.
// Fused finish: last block writes sqrt(change) via completion counter.
// ---------------------------------------------------------------------------
__global__ __launch_bounds__(128)
void attractor_kernel(const float* __restrict__ emb,
                      const float* __restrict__ attr,
                      float* __restrict__ out_field,
                      float* __restrict__ out_chg)
{
    __shared__ float4 sA[N_ATT][32];     // recon layout: dims packed
    __shared__ F2     sA2[5][128];       // init layout: attractor pairs per dim
    __shared__ F2     sG2[5][N_ATT];     // Gram rows packed over row-pairs
    __shared__ float  red[4];

    const int tid = threadIdx.x;
    for (int i = tid; i < N_ATT * 32; i += blockDim.x) {
        int a = i / 32, c = i % 32;
        sA[a][c] = reinterpret_cast<const float4*>(attr)[a * 32 + c];
    }
    for (int i = tid; i < 5 * N_ATT; i += blockDim.x) {
        int p = i / N_ATT, b = i % N_ATT;
        sG2[p][b] = f2pack(g_Gram[(2 * p) * N_ATT + b], g_Gram[(2 * p + 1) * N_ATT + b]);
    }
    for (int i = tid; i < 5 * 128; i += blockDim.x) {
        int p = i / 128, d = i % 128;
        sA2[p][d] = f2pack(attr[(2 * p) * 128 + d], attr[(2 * p + 1) * 128 + d]);
    }
    __syncthreads();

    const int tok = blockIdx.x * blockDim.x + tid;
    const float4* e4 = reinterpret_cast<const float4*>(emb + (size_t)tok * D_DIM);
    const F2* e2 = reinterpret_cast<const F2*>(emb + (size_t)tok * D_DIM);

    // diag pairs from global (cached)
    F2 diagp[5];
    #pragma unroll
    for (int p = 0; p < 5; p++)
        diagp[p] = f2pack(g_Gram[(2 * p) * N_ATT + 2 * p],
                          g_Gram[(2 * p + 1) * N_ATT + 2 * p + 1]);

    // ---- init: g_a = A_a . p0 (packed over attractor pairs), q = |p0|^2 ----
    F2 gp[5];
    #pragma unroll
    for (int p = 0; p < 5; p++) gp[p] = F2_ZERO;
    F2 qp = F2_ZERO;
    #pragma unroll 4
    for (int d2i = 0; d2i < 64; d2i++) {
        F2 e = e2[d2i];
        qp = f2fma(e, e, qp);
        float ea, eb; f2unpack(e, ea, eb);
        F2 da = f2dup(ea), db = f2dup(eb);
        #pragma unroll
        for (int p = 0; p < 5; p++) {
            gp[p] = f2fma(da, sA2[p][2 * d2i],     gp[p]);
            gp[p] = f2fma(db, sA2[p][2 * d2i + 1], gp[p]);
        }
    }
    float q = f2hadd(qp);

    // seed packed rsqrt (only MUFU use)
    F2 rp[5];
    {
        F2 qd = f2dup(q), m2 = f2dup(-2.f);
        #pragma unroll
        for (int p = 0; p < 5; p++) {
            F2 d2v = f2fma(gp[p], m2, qd);
            d2v = f2fma(diagp[p], F2_ONE, d2v);
            float a, b; f2unpack(d2v, a, b);
            rp[p] = f2pack(rsqrtf(a), rsqrtf(b));
        }
    }

    F2 Wp[5];
    #pragma unroll
    for (int p = 0; p < 5; p++) Wp[p] = F2_ZERO;
    float Atot = 1.f;
    const F2 SGD   = f2dup(STEPSZ * GRAV);
    const F2 M2D   = f2dup(-2.f);
    const F2 MHALF = f2dup(-0.5f);
    const F2 C15   = f2dup(1.5f);

    F2 sp[5];
    float S = 0.f;

    #pragma unroll 1
    for (int t = 0; t < N_ITERS - 1; t++) {
        F2 qd = f2dup(q);
        F2 ssum = F2_ZERO, sgacc = F2_ZERO;
        #pragma unroll
        for (int p = 0; p < 5; p++) {
            F2 d2v = f2fma(gp[p], M2D, qd);
            d2v = f2fma(diagp[p], F2_ONE, d2v);
            F2 rr = rp[p];
            F2 rr2 = f2fma(rr, rr, F2_ZERO);
            F2 u   = f2fma(d2v, rr2, F2_ZERO);
            F2 tt  = f2fma(u, MHALF, C15);
            rr = f2fma(rr, tt, F2_ZERO);          // Newton refresh
            rp[p] = rr;
            F2 rr2b = f2fma(rr, rr, F2_ZERO);
            F2 sgr  = f2fma(rr, SGD, F2_ZERO);
            F2 ss   = f2fma(rr2b, sgr, F2_ZERO);  // SG * rr^3
            sp[p] = ss;
            ssum  = f2fma(ss, F2_ONE, ssum);
            sgacc = f2fma(ss, gp[p], sgacc);
        }
        S = f2hadd(ssum);
        float sg = f2hadd(sgacc);

        // scalar s + dups for matvec
        float sc[10];
        #pragma unroll
        for (int p = 0; p < 5; p++) f2unpack(sp[p], sc[2 * p], sc[2 * p + 1]);
        F2 sd[10];
        #pragma unroll
        for (int b = 0; b < 10; b++) sd[b] = f2dup(sc[b]);

        F2 svacc = F2_ZERO;
        F2 vp[5];
        #pragma unroll
        for (int p = 0; p < 5; p++) {
            F2 acc2 = F2_ZERO;
            #pragma unroll
            for (int b = 0; b < 10; b++)
                acc2 = f2fma(sd[b], sG2[p][b], acc2);
            vp[p] = acc2;
            svacc = f2fma(sp[p], acc2, svacc);
        }
        float sv = f2hadd(svacc);

        float alpha = 1.f - S;
        q = alpha * alpha * q + 2.f * alpha * sg + sv;
        F2 ad = f2dup(alpha);
        #pragma unroll
        for (int p = 0; p < 5; p++) {
            gp[p] = f2fma(ad, gp[p], vp[p]);
            Wp[p] = f2fma(ad, Wp[p], sp[p]);
        }
        Atot *= alpha;
    }

    // step-50 coefficients
    {
        F2 qd = f2dup(q);
        F2 ssum = F2_ZERO;
        #pragma unroll
        for (int p = 0; p < 5; p++) {
            F2 d2v = f2fma(gp[p], M2D, qd);
            d2v = f2fma(diagp[p], F2_ONE, d2v);
            F2 rr = rp[p];
            F2 rr2 = f2fma(rr, rr, F2_ZERO);
            F2 u   = f2fma(d2v, rr2, F2_ZERO);
            F2 tt  = f2fma(u, MHALF, C15);
            rr = f2fma(rr, tt, F2_ZERO);
            F2 rr2b = f2fma(rr, rr, F2_ZERO);
            F2 sgr  = f2fma(rr, SGD, F2_ZERO);
            sp[p] = f2fma(rr2b, sgr, F2_ZERO);
            ssum  = f2fma(sp[p], F2_ONE, ssum);
        }
        S = f2hadd(ssum);
    }

    // unpack to scalars for the recon epilogue
    float W[N_ATT], s[N_ATT];
    #pragma unroll
    for (int p = 0; p < 5; p++) {
        f2unpack(Wp[p], W[2 * p], W[2 * p + 1]);
        f2unpack(sp[p], s[2 * p], s[2 * p + 1]);
    }

    // ---- recon: p49 per element, explicit fp32 step, quantized change ----
    float chg2 = 0.f;
    float4* o4 = reinterpret_cast<float4*>(out_field + (size_t)tok * D_DIM);
    uint4* fh4 = reinterpret_cast<uint4*>(g_Fhi + (size_t)tok * D_DIM);
    uint4* fl4 = reinterpret_cast<uint4*>(g_Flo + (size_t)tok * D_DIM);

    #pragma unroll
    for (int batch = 0; batch < 4; batch++) {
        uint32_t hbuf[16], lbuf[16];
        #pragma unroll
        for (int j = 0; j < 8; j++) {
            const int c = batch * 8 + j;
            float4 e = e4[c];
            float px = Atot*e.x, py = Atot*e.y, pz = Atot*e.z, pw = Atot*e.w;
            float fx = 0.f, fy = 0.f, fz = 0.f, fw = 0.f;
            #pragma unroll
            for (int a = 0; a < N_ATT; a++) {
                float4 av = sA[a][c];
                px += W[a]*av.x; py += W[a]*av.y; pz += W[a]*av.z; pw += W[a]*av.w;
                fx += s[a]*av.x; fy += s[a]*av.y; fz += s[a]*av.z; fw += s[a]*av.w;
            }
            float nx = px + (fx - S*px);
            float ny = py + (fy - S*py);
            float nz = pz + (fz - S*pz);
            float nw = pw + (fw - S*pw);
            float dx = nx-px, dy = ny-py, dz = nz-pz, dw = nw-pw;
            chg2 += dx*dx + dy*dy + dz*dz + dw*dw;
            o4[c] = make_float4(nx, ny, nz, nw);
            split_pack2(nx, ny, hbuf[j*2],   lbuf[j*2]);
            split_pack2(nz, nw, hbuf[j*2+1], lbuf[j*2+1]);
        }
        #pragma unroll
        for (int j = 0; j < 4; j++) {
            fh4[batch * 4 + j] = make_uint4(hbuf[j*4], hbuf[j*4+1], hbuf[j*4+2], hbuf[j*4+3]);
            fl4[batch * 4 + j] = make_uint4(lbuf[j*4], lbuf[j*4+1], lbuf[j*4+2], lbuf[j*4+3]);
        }
    }

    #pragma unroll
    for (int sft = 16; sft > 0; sft >>= 1)
        chg2 += __shfl_xor_sync(0xFFFFFFFFu, chg2, sft);
    if ((tid & 31) == 0) red[tid >> 5] = chg2;
    __syncthreads();
    if (tid == 0) {
        atomicAdd(&g_change, red[0] + red[1] + red[2] + red[3]);
        __threadfence();
        int n = atomicAdd(&g_done, 1);
        if (n == (int)gridDim.x - 1) {
            float total = atomicAdd(&g_change, 0.f);   // ordered read
            out_chg[0] = sqrtf(total);
        }
    }
}

// ---------------------------------------------------------------------------
extern "C" void kernel_launch(void* const* d_in, const int* in_sizes, int n_in,
                              void* d_out, int out_size)
{
    const float* text   = (const float*)d_in[0];
    const float* enc_w1 = (const float*)d_in[1];
    const float* enc_b1 = (const float*)d_in[2];
    const float* enc_w2 = (const float*)d_in[3];
    const float* enc_b2 = (const float*)d_in[4];
    const float* attr   = (const float*)d_in[5];
    const float* dec_w1 = (const float*)d_in[6];
    const float* dec_b1 = (const float*)d_in[7];
    const float* dec_w2 = (const float*)d_in[8];
    const float* dec_b2 = (const float*)d_in[9];

    float* out       = (float*)d_out;
    float* out_field = out;
    float* out_rec   = out + OUT_FIELD_ELEMS;
    float* out_chg   = out + OUT_FIELD_ELEMS + OUT_REC_ELEMS;

    bf16 *Thi, *Tlo, *Hhi, *Hlo, *Fhi, *Flo;
    bf16 *W1hi, *W1lo, *W2hi, *W2lo, *W3hi, *W3lo, *W4hi, *W4lo;
    float* EMB;
    cudaGetSymbolAddress((void**)&Thi,  g_Thi);  cudaGetSymbolAddress((void**)&Tlo,  g_Tlo);
    cudaGetSymbolAddress((void**)&Hhi,  g_Hhi);  cudaGetSymbolAddress((void**)&Hlo,  g_Hlo);
    cudaGetSymbolAddress((void**)&Fhi,  g_Fhi);  cudaGetSymbolAddress((void**)&Flo,  g_Flo);
    cudaGetSymbolAddress((void**)&W1hi, g_W1hi); cudaGetSymbolAddress((void**)&W1lo, g_W1lo);
    cudaGetSymbolAddress((void**)&W2hi, g_W2hi); cudaGetSymbolAddress((void**)&W2lo, g_W2lo);
    cudaGetSymbolAddress((void**)&W3hi, g_W3hi); cudaGetSymbolAddress((void**)&W3lo, g_W3lo);
    cudaGetSymbolAddress((void**)&W4hi, g_W4hi); cudaGetSymbolAddress((void**)&W4lo, g_W4lo);
    cudaGetSymbolAddress((void**)&EMB,  g_EMB);

    // Fused prep (text+weights split, Gram, resets) — one launch
    prep_kernel<<<8705, 256>>>(text, enc_w1, enc_w2, dec_w1, dec_w2, attr);

    // enc1: [M,100p128] @ W1 -> relu -> H (bf16 split), N=256
    mma_gemm<true, true><<<dim3(M_TOK / 128, 4), 256>>>(
        Thi, Tlo, 128, W1hi, W1lo, 128, enc_b1,
        nullptr, Hhi, Hlo, 256, 256, 2);
    // enc2: [M,256] @ W2 -> EMB fp32, N=128
    mma_gemm<false, false><<<dim3(M_TOK / 128, 2), 256>>>(
        Hhi, Hlo, 256, W2hi, W2lo, 256, enc_b2,
        EMB, nullptr, nullptr, 128, 128, 4);

    // Attractor (packed fp32x2 dual loop) + fused finish
    attractor_kernel<<<M_TOK / 128, 128>>>(EMB, attr, out_field, out_chg);

    // dec1: [M,128] @ W3 -> relu -> H (bf16 split), N=256
    mma_gemm<true, true><<<dim3(M_TOK / 128, 4), 256>>>(
        Fhi, Flo, 128, W3hi, W3lo, 128, dec_b1,
        nullptr, Hhi, Hlo, 256, 256, 2);
    // dec2: [M,256] @ W4 -> out_rec fp32, N=100 (ldc=100)
    mma_gemm<false, false><<<dim3(M_TOK / 128, 2), 256>>>(
        Hhi, Hlo, 256, W4hi, W4lo, 256, dec_b2,
        out_rec, nullptr, nullptr, 100, 100, 4);
}

// round 16
// speedup vs baseline: 1.3767x; 1.0556x over previous
#include <cuda_runtime.h>
#include <cuda_bf16.h>
#include <cstdint>

typedef __nv_bfloat16 bf16;
typedef unsigned long long F2;   // packed fp32x2

#define M_TOK   32768
#define D_DIM   128
#define N_ATT   10
#define GRAV    0.001f
#define STEPSZ  0.01f
#define N_ITERS 50

#define OUT_FIELD_ELEMS (M_TOK * 128)
#define OUT_REC_ELEMS   (M_TOK * 100)

// ---------------- device scratch (allocation-free rule) --------------------
__device__ bf16  g_Thi[M_TOK * 128], g_Tlo[M_TOK * 128];   // text, K padded 100->128
__device__ bf16  g_Hhi[M_TOK * 256], g_Hlo[M_TOK * 256];   // hidden (enc1/dec1 out)
__device__ bf16  g_Fhi[M_TOK * 128], g_Flo[M_TOK * 128];   // attractor field split
__device__ float g_EMB[M_TOK * 128];                       // enc2 out (fp32)
__device__ bf16  g_W1hi[256 * 128], g_W1lo[256 * 128];     // [N,Kpad] K-major
__device__ bf16  g_W2hi[128 * 256], g_W2lo[128 * 256];
__device__ bf16  g_W3hi[256 * 128], g_W3lo[256 * 128];
__device__ bf16  g_W4hi[128 * 256], g_W4lo[128 * 256];     // N 100->128 padded
__device__ float g_Gram[N_ATT * N_ATT];
__device__ float g_change;
__device__ int   g_done;

// ---------------- helpers ---------------------------------------------------
__device__ __forceinline__ uint32_t smem_u32(const void* p) {
    uint32_t a;
    asm("{ .reg .u64 t; cvta.to.shared.u64 t, %1; cvt.u32.u64 %0, t; }" : "=r"(a) : "l"(p));
    return a;
}
#define SWZ(off) ((off) ^ (((off) >> 3) & 0x70))

#define CP_ASYNC16(dst, src) \
    asm volatile("cp.async.ca.shared.global [%0], [%1], 16;" :: "r"(dst), "l"(src))
#define CP_COMMIT() asm volatile("cp.async.commit_group;" ::: "memory")
#define CP_WAIT1()  asm volatile("cp.async.wait_group 1;" ::: "memory")
#define CP_WAIT0()  asm volatile("cp.async.wait_group 0;" ::: "memory")

#define LDSM_X4(r0, r1, r2, r3, addr) \
    asm volatile("ldmatrix.sync.aligned.m8n8.x4.shared.b16 {%0,%1,%2,%3}, [%4];" \
        : "=r"(r0), "=r"(r1), "=r"(r2), "=r"(r3) : "r"(addr))

#define MMA16816(d, a0, a1, a2, a3, b0, b1) \
    asm volatile("mma.sync.aligned.m16n8k16.row.col.f32.bf16.bf16.f32 " \
        "{%0,%1,%2,%3}, {%4,%5,%6,%7}, {%8,%9}, {%0,%1,%2,%3};" \
        : "+f"((d)[0]), "+f"((d)[1]), "+f"((d)[2]), "+f"((d)[3]) \
        : "r"(a0), "r"(a1), "r"(a2), "r"(a3), "r"(b0), "r"(b1))

__device__ __forceinline__ void split2(float v, bf16& hi, bf16& lo) {
    hi = __float2bfloat16(v);
    lo = __float2bfloat16(v - __bfloat162float(hi));
}

__device__ __forceinline__ void split_pack2(float a, float b,
                                            uint32_t& hw, uint32_t& lw) {
    bf16 ha, la, hb, lb;
    split2(a, ha, la); split2(b, hb, lb);
    __nv_bfloat162 hp; hp.x = ha; hp.y = hb;
    __nv_bfloat162 lp; lp.x = la; lp.y = lb;
    hw = *reinterpret_cast<uint32_t*>(&hp);
    lw = *reinterpret_cast<uint32_t*>(&lp);
}

// ---- fp32x2 packed ops (fma.rn.f32x2, proven on this harness) -------------
__device__ __forceinline__ F2 f2fma(F2 a, F2 b, F2 c) {
    F2 d; asm("fma.rn.f32x2 %0, %1, %2, %3;" : "=l"(d) : "l"(a), "l"(b), "l"(c));
    return d;
}
__device__ __forceinline__ F2 f2dup(float x) {
    F2 r; uint32_t b = __float_as_uint(x);
    asm("mov.b64 %0, {%1, %1};" : "=l"(r) : "r"(b));
    return r;
}
__device__ __forceinline__ F2 f2pack(float a, float b) {
    F2 r;
    asm("mov.b64 %0, {%1, %2};" : "=l"(r)
        : "r"(__float_as_uint(a)), "r"(__float_as_uint(b)));
    return r;
}
__device__ __forceinline__ void f2unpack(F2 v, float& a, float& b) {
    uint32_t x, y;
    asm("mov.b64 {%0, %1}, %2;" : "=r"(x), "=r"(y) : "l"(v));
    a = __uint_as_float(x); b = __uint_as_float(y);
}
__device__ __forceinline__ float f2hadd(F2 v) {
    float a, b; f2unpack(v, a, b); return a + b;
}
#define F2_ZERO 0ULL
#define F2_ONE  0x3F8000003F800000ULL

// ---------------------------------------------------------------------------
// bf16x3-split tensor-core GEMM, cp.async double-buffered (R12, unchanged).
// ---------------------------------------------------------------------------
#define STAGE_BYTES 24576

template<bool RELU, bool SPLIT>
__global__ __launch_bounds__(256)
void mma_gemm(const bf16* __restrict__ Ahi, const bf16* __restrict__ Alo, int lda,
              const bf16* __restrict__ Bhi, const bf16* __restrict__ Blo, int ldb,
              const float* __restrict__ bias,
              float* __restrict__ Cf, bf16* __restrict__ Chi, bf16* __restrict__ Clo,
              int ldc, int N_out, int nc)
{
    __shared__ alignas(1024) char smem[2 * STAGE_BYTES];
    const uint32_t sbase = smem_u32(smem);

    const int tid = threadIdx.x;
    const int wid = tid >> 5, lid = tid & 31;
    const int bm = blockIdx.x * 128, bn = blockIdx.y * 64;
    const int warpM = wid >> 1, warpN = wid & 1;
    const int m_base = warpM * 32, n_base = warpN * 32;
    const int phase = lid >> 3, r_in = lid & 7;
    const int lr = tid >> 3, lc = tid & 7;

    const int nch = 3 * nc;

    float acc[2][4][4];
    #pragma unroll
    for (int mt = 0; mt < 2; mt++)
        #pragma unroll
        for (int nt = 0; nt < 4; nt++)
            #pragma unroll
            for (int e = 0; e < 4; e++) acc[mt][nt][e] = 0.f;

    auto issue = [&](int c, int st) {
        const bf16 *Ab, *Bb; int ka;
        if (c < nc)          { Ab = Ahi; Bb = Bhi; ka = c; }
        else if (c < 2 * nc) { Ab = Ahi; Bb = Blo; ka = c - nc; }
        else                 { Ab = Alo; Bb = Bhi; ka = c - 2 * nc; }
        const bf16* Ag = Ab + (size_t)bm * lda + ka * 64;
        const bf16* Bg = Bb + (size_t)bn * ldb + ka * 64;
        const uint32_t aOff = sbase + st * STAGE_BYTES;
        const uint32_t bOff = aOff + 16384;
        #pragma unroll
        for (int i = 0; i < 4; i++)
            CP_ASYNC16(aOff + SWZ((lr + i * 32) * 128 + lc * 16),
                       Ag + (size_t)(lr + i * 32) * lda + lc * 8);
        #pragma unroll
        for (int i = 0; i < 2; i++)
            CP_ASYNC16(bOff + SWZ((lr + i * 32) * 128 + lc * 16),
                       Bg + (size_t)(lr + i * 32) * ldb + lc * 8);
        CP_COMMIT();
    };

    issue(0, 0);

    for (int c = 0; c < nch; c++) {
        if (c + 1 < nch) { issue(c + 1, (c + 1) & 1); CP_WAIT1(); }
        else             { CP_WAIT0(); }
        __syncthreads();

        const uint32_t sA = sbase + (c & 1) * STAGE_BYTES;
        const uint32_t sB = sA + 16384;
        #pragma unroll
        for (int k16 = 0; k16 < 4; k16++) {
            const int kb = k16 * 32;
            uint32_t af[2][4], bfr[2][4];
            #pragma unroll
            for (int mt = 0; mt < 2; mt++) {
                int row = m_base + mt * 16 + ((phase & 1) << 3) + r_in;
                int col = kb + ((phase >> 1) << 4);
                LDSM_X4(af[mt][0], af[mt][1], af[mt][2], af[mt][3],
                        sA + SWZ(row * 128 + col));
            }
            #pragma unroll
            for (int ng = 0; ng < 2; ng++) {
                int row = n_base + ng * 16 + ((phase >> 1) << 3) + r_in;
                int col = kb + ((phase & 1) << 4);
                LDSM_X4(bfr[ng][0], bfr[ng][1], bfr[ng][2], bfr[ng][3],
                        sB + SWZ(row * 128 + col));
            }
            #pragma unroll
            for (int mt = 0; mt < 2; mt++)
                #pragma unroll
                for (int ng = 0; ng < 2; ng++) {
                    MMA16816(acc[mt][ng * 2 + 0],
                             af[mt][0], af[mt][1], af[mt][2], af[mt][3],
                             bfr[ng][0], bfr[ng][1]);
                    MMA16816(acc[mt][ng * 2 + 1],
                             af[mt][0], af[mt][1], af[mt][2], af[mt][3],
                             bfr[ng][2], bfr[ng][3]);
                }
        }
        __syncthreads();
    }

    const int g = lid >> 2, t2 = (lid & 3) * 2;
    #pragma unroll
    for (int mt = 0; mt < 2; mt++) {
        const int m0r = bm + m_base + mt * 16 + g;
        #pragma unroll
        for (int nt = 0; nt < 4; nt++) {
            const int n = bn + n_base + nt * 8 + t2;
            float b0v = (n < N_out)     ? bias[n]     : 0.f;
            float b1v = (n + 1 < N_out) ? bias[n + 1] : 0.f;
            float v0 = acc[mt][nt][0] + b0v, v1 = acc[mt][nt][1] + b1v;
            float v2 = acc[mt][nt][2] + b0v, v3 = acc[mt][nt][3] + b1v;
            if (RELU) {
                v0 = fmaxf(v0, 0.f); v1 = fmaxf(v1, 0.f);
                v2 = fmaxf(v2, 0.f); v3 = fmaxf(v3, 0.f);
            }
            if (SPLIT) {
                uint32_t hw, lw;
                split_pack2(v0, v1, hw, lw);
                *reinterpret_cast<uint32_t*>(Chi + (size_t)m0r * ldc + n) = hw;
                *reinterpret_cast<uint32_t*>(Clo + (size_t)m0r * ldc + n) = lw;
                split_pack2(v2, v3, hw, lw);
                *reinterpret_cast<uint32_t*>(Chi + (size_t)(m0r + 8) * ldc + n) = hw;
                *reinterpret_cast<uint32_t*>(Clo + (size_t)(m0r + 8) * ldc + n) = lw;
            } else if (n < N_out) {
                *reinterpret_cast<float2*>(Cf + (size_t)m0r * ldc + n)       = make_float2(v0, v1);
                *reinterpret_cast<float2*>(Cf + (size_t)(m0r + 8) * ldc + n) = make_float2(v2, v3);
            }
        }
    }
}

// ---------------------------------------------------------------------------
// Fused prep: text split (pairs) + 4 weight splits + Gram + resets.
// ---------------------------------------------------------------------------
__device__ __forceinline__ void wsplit_blk(const float* __restrict__ W,
                                           bf16* __restrict__ Bhi, bf16* __restrict__ Blo,
                                           int K, int N, int K_pad, int blk)
{
    int idx = blk * 256 + threadIdx.x;
    int n = idx / K_pad, k = idx % K_pad;
    float v = (n < N && k < K) ? W[(size_t)k * N + n] : 0.f;
    bf16 h, l; split2(v, h, l);
    Bhi[idx] = h; Blo[idx] = l;
}

__global__ void prep_kernel(const float* __restrict__ text,
                            const float* __restrict__ w1, const float* __restrict__ w2,
                            const float* __restrict__ w3, const float* __restrict__ w4,
                            const float* __restrict__ attr)
{
    int b = blockIdx.x;
    if (b < 8192) {
        int idx = b * 256 + threadIdx.x;   // pair index over M_TOK*64
        int m = idx >> 6, kp = idx & 63;
        float2 v = make_float2(0.f, 0.f);
        if (kp < 50) v = *reinterpret_cast<const float2*>(text + (size_t)m * 100 + 2 * kp);
        uint32_t hw, lw;
        split_pack2(v.x, v.y, hw, lw);
        reinterpret_cast<uint32_t*>(g_Thi)[idx] = hw;
        reinterpret_cast<uint32_t*>(g_Tlo)[idx] = lw;
    } else if (b < 8320) {
        wsplit_blk(w1, g_W1hi, g_W1lo, 100, 256, 128, b - 8192);
    } else if (b < 8448) {
        wsplit_blk(w2, g_W2hi, g_W2lo, 256, 128, 256, b - 8320);
    } else if (b < 8576) {
        wsplit_blk(w3, g_W3hi, g_W3lo, 128, 256, 128, b - 8448);
    } else if (b < 8704) {
        wsplit_blk(w4, g_W4hi, g_W4lo, 256, 100, 256, b - 8576);
    } else {
        int i = threadIdx.x;
        if (i == 0) { g_change = 0.f; g_done = 0; }
        if (i < N_ATT * N_ATT) {
            int a = i / N_ATT, bb = i % N_ATT;
            float s = 0.f;
            for (int d = 0; d < D_DIM; d++)
                s += attr[a * D_DIM + d] * attr[bb * D_DIM + d];
            g_Gram[i] = s;
        }
    }
}

// ---------------------------------------------------------------------------
// Attractor dynamics: GROUPED closed-form dual-space evolution.
// The per-step coefficients s_a drift by only ~1e-7 relative per iteration
// (total displacement over 50 steps is ~1e-5 |p|), so s is frozen over
// groups of 7 steps and the exact frozen-s closed form is applied:
//   beta = alpha^7,  gamma = sum_{i<7} alpha^i = (1+a)(1+a^2)(1+a^4) - beta
//   g' = beta*g + gamma*v;  W' = beta*W + gamma*s
//   q' = beta^2*q + 2*beta*gamma*(s.g) + gamma^2*(s^T G s);  Atot *= beta
// 7 groups cover the 49 pre-final steps; the 50th step stays explicit in
// fp32 element space (quantization-faithful change, fresh s). Packed fp32x2
// over attractor pairs, Newton-maintained rsqrt (one refresh per group).
// ---------------------------------------------------------------------------
__global__ __launch_bounds__(128)
void attractor_kernel(const float* __restrict__ emb,
                      const float* __restrict__ attr,
                      float* __restrict__ out_field,
                      float* __restrict__ out_chg)
{
    __shared__ float4 sA[N_ATT][32];     // recon layout: dims packed
    __shared__ F2     sA2[5][128];       // init layout: attractor pairs per dim
    __shared__ F2     sG2[5][N_ATT];     // Gram rows packed over row-pairs
    __shared__ float  red[4];

    const int tid = threadIdx.x;
    for (int i = tid; i < N_ATT * 32; i += blockDim.x) {
        int a = i / 32, c = i % 32;
        sA[a][c] = reinterpret_cast<const float4*>(attr)[a * 32 + c];
    }
    for (int i = tid; i < 5 * N_ATT; i += blockDim.x) {
        int p = i / N_ATT, b = i % N_ATT;
        sG2[p][b] = f2pack(g_Gram[(2 * p) * N_ATT + b], g_Gram[(2 * p + 1) * N_ATT + b]);
    }
    for (int i = tid; i < 5 * 128; i += blockDim.x) {
        int p = i / 128, d = i % 128;
        sA2[p][d] = f2pack(attr[(2 * p) * 128 + d], attr[(2 * p + 1) * 128 + d]);
    }
    __syncthreads();

    const int tok = blockIdx.x * blockDim.x + tid;
    const float4* e4 = reinterpret_cast<const float4*>(emb + (size_t)tok * D_DIM);
    const F2* e2 = reinterpret_cast<const F2*>(emb + (size_t)tok * D_DIM);

    // diag pairs from global (cached)
    F2 diagp[5];
    #pragma unroll
    for (int p = 0; p < 5; p++)
        diagp[p] = f2pack(g_Gram[(2 * p) * N_ATT + 2 * p],
                          g_Gram[(2 * p + 1) * N_ATT + 2 * p + 1]);

    // ---- init: g_a = A_a . p0 (packed over attractor pairs), q = |p0|^2 ----
    F2 gp[5];
    #pragma unroll
    for (int p = 0; p < 5; p++) gp[p] = F2_ZERO;
    F2 qp = F2_ZERO;
    #pragma unroll 4
    for (int d2i = 0; d2i < 64; d2i++) {
        F2 e = e2[d2i];
        qp = f2fma(e, e, qp);
        float ea, eb; f2unpack(e, ea, eb);
        F2 da = f2dup(ea), db = f2dup(eb);
        #pragma unroll
        for (int p = 0; p < 5; p++) {
            gp[p] = f2fma(da, sA2[p][2 * d2i],     gp[p]);
            gp[p] = f2fma(db, sA2[p][2 * d2i + 1], gp[p]);
        }
    }
    float q = f2hadd(qp);

    // seed packed rsqrt (only MUFU use besides final sqrt)
    F2 rp[5];
    {
        F2 qd = f2dup(q), m2 = f2dup(-2.f);
        #pragma unroll
        for (int p = 0; p < 5; p++) {
            F2 d2v = f2fma(gp[p], m2, qd);
            d2v = f2fma(diagp[p], F2_ONE, d2v);
            float a, b; f2unpack(d2v, a, b);
            rp[p] = f2pack(rsqrtf(a), rsqrtf(b));
        }
    }

    F2 Wp[5];
    #pragma unroll
    for (int p = 0; p < 5; p++) Wp[p] = F2_ZERO;
    float Atot = 1.f;
    const F2 SGD   = f2dup(STEPSZ * GRAV);
    const F2 M2D   = f2dup(-2.f);
    const F2 MHALF = f2dup(-0.5f);
    const F2 C15   = f2dup(1.5f);

    F2 sp[5];
    float S = 0.f;

    // 7 groups x 7 frozen steps = the 49 pre-final iterations
    #pragma unroll 1
    for (int grp = 0; grp < 7; grp++) {
        F2 qd = f2dup(q);
        F2 ssum = F2_ZERO, sgacc = F2_ZERO;
        #pragma unroll
        for (int p = 0; p < 5; p++) {
            F2 d2v = f2fma(gp[p], M2D, qd);
            d2v = f2fma(diagp[p], F2_ONE, d2v);
            F2 rr = rp[p];
            F2 rr2 = f2fma(rr, rr, F2_ZERO);
            F2 u   = f2fma(d2v, rr2, F2_ZERO);
            F2 tt  = f2fma(u, MHALF, C15);
            rr = f2fma(rr, tt, F2_ZERO);          // Newton refresh
            rp[p] = rr;
            F2 rr2b = f2fma(rr, rr, F2_ZERO);
            F2 sgr  = f2fma(rr, SGD, F2_ZERO);
            F2 ss   = f2fma(rr2b, sgr, F2_ZERO);  // SG * rr^3
            sp[p] = ss;
            ssum  = f2fma(ss, F2_ONE, ssum);
            sgacc = f2fma(ss, gp[p], sgacc);
        }
        S = f2hadd(ssum);
        float sg = f2hadd(sgacc);

        // scalar s + dups for matvec
        float sc[10];
        #pragma unroll
        for (int p = 0; p < 5; p++) f2unpack(sp[p], sc[2 * p], sc[2 * p + 1]);
        F2 sd[10];
        #pragma unroll
        for (int b = 0; b < 10; b++) sd[b] = f2dup(sc[b]);

        F2 svacc = F2_ZERO;
        F2 vp[5];
        #pragma unroll
        for (int p = 0; p < 5; p++) {
            F2 acc2 = F2_ZERO;
            #pragma unroll
            for (int b = 0; b < 10; b++)
                acc2 = f2fma(sd[b], sG2[p][b], acc2);
            vp[p] = acc2;
            svacc = f2fma(sp[p], acc2, svacc);
        }
        float sv = f2hadd(svacc);

        // frozen-s closed form over 7 steps
        float alpha = 1.f - S;
        float a2 = alpha * alpha;
        float a4 = a2 * a2;
        float beta = a4 * a2 * alpha;                         // alpha^7
        float gam  = (1.f + alpha) * (1.f + a2) * (1.f + a4) - beta;  // sum_{i<7} alpha^i

        q = beta * beta * q + 2.f * beta * gam * sg + gam * gam * sv;
        F2 bd = f2dup(beta), gd = f2dup(gam);
        #pragma unroll
        for (int p = 0; p < 5; p++) {
            F2 gv = f2fma(gd, vp[p], F2_ZERO);
            gp[p] = f2fma(bd, gp[p], gv);
            F2 gs = f2fma(gd, sp[p], F2_ZERO);
            Wp[p] = f2fma(bd, Wp[p], gs);
        }
        Atot *= beta;
    }

    // step-50 coefficients (fresh s at p49)
    {
        F2 qd = f2dup(q);
        F2 ssum = F2_ZERO;
        #pragma unroll
        for (int p = 0; p < 5; p++) {
            F2 d2v = f2fma(gp[p], M2D, qd);
            d2v = f2fma(diagp[p], F2_ONE, d2v);
            F2 rr = rp[p];
            F2 rr2 = f2fma(rr, rr, F2_ZERO);
            F2 u   = f2fma(d2v, rr2, F2_ZERO);
            F2 tt  = f2fma(u, MHALF, C15);
            rr = f2fma(rr, tt, F2_ZERO);
            F2 rr2b = f2fma(rr, rr, F2_ZERO);
            F2 sgr  = f2fma(rr, SGD, F2_ZERO);
            sp[p] = f2fma(rr2b, sgr, F2_ZERO);
            ssum  = f2fma(sp[p], F2_ONE, ssum);
        }
        S = f2hadd(ssum);
    }

    // unpack to scalars for the recon epilogue
    float W[N_ATT], s[N_ATT];
    #pragma unroll
    for (int p = 0; p < 5; p++) {
        f2unpack(Wp[p], W[2 * p], W[2 * p + 1]);
        f2unpack(sp[p], s[2 * p], s[2 * p + 1]);
    }

    // ---- recon: p49 per element, explicit fp32 step, quantized change ----
    float chg2 = 0.f;
    float4* o4 = reinterpret_cast<float4*>(out_field + (size_t)tok * D_DIM);
    uint4* fh4 = reinterpret_cast<uint4*>(g_Fhi + (size_t)tok * D_DIM);
    uint4* fl4 = reinterpret_cast<uint4*>(g_Flo + (size_t)tok * D_DIM);

    #pragma unroll
    for (int batch = 0; batch < 4; batch++) {
        uint32_t hbuf[16], lbuf[16];
        #pragma unroll
        for (int j = 0; j < 8; j++) {
            const int c = batch * 8 + j;
            float4 e = e4[c];
            float px = Atot*e.x, py = Atot*e.y, pz = Atot*e.z, pw = Atot*e.w;
            float fx = 0.f, fy = 0.f, fz = 0.f, fw = 0.f;
            #pragma unroll
            for (int a = 0; a < N_ATT; a++) {
                float4 av = sA[a][c];
                px += W[a]*av.x; py += W[a]*av.y; pz += W[a]*av.z; pw += W[a]*av.w;
                fx += s[a]*av.x; fy += s[a]*av.y; fz += s[a]*av.z; fw += s[a]*av.w;
            }
            float nx = px + (fx - S*px);
            float ny = py + (fy - S*py);
            float nz = pz + (fz - S*pz);
            float nw = pw + (fw - S*pw);
            float dx = nx-px, dy = ny-py, dz = nz-pz, dw = nw-pw;
            chg2 += dx*dx + dy*dy + dz*dz + dw*dw;
            o4[c] = make_float4(nx, ny, nz, nw);
            split_pack2(nx, ny, hbuf[j*2],   lbuf[j*2]);
            split_pack2(nz, nw, hbuf[j*2+1], lbuf[j*2+1]);
        }
        #pragma unroll
        for (int j = 0; j < 4; j++) {
            fh4[batch * 4 + j] = make_uint4(hbuf[j*4], hbuf[j*4+1], hbuf[j*4+2], hbuf[j*4+3]);
            fl4[batch * 4 + j] = make_uint4(lbuf[j*4], lbuf[j*4+1], lbuf[j*4+2], lbuf[j*4+3]);
        }
    }

    #pragma unroll
    for (int sft = 16; sft > 0; sft >>= 1)
        chg2 += __shfl_xor_sync(0xFFFFFFFFu, chg2, sft);
    if ((tid & 31) == 0) red[tid >> 5] = chg2;
    __syncthreads();
    if (tid == 0) {
        atomicAdd(&g_change, red[0] + red[1] + red[2] + red[3]);
        __threadfence();
        int n = atomicAdd(&g_done, 1);
        if (n == (int)gridDim.x - 1) {
            float total = atomicAdd(&g_change, 0.f);   // ordered read
            out_chg[0] = sqrtf(total);
        }
    }
}

// ---------------------------------------------------------------------------
extern "C" void kernel_launch(void* const* d_in, const int* in_sizes, int n_in,
                              void* d_out, int out_size)
{
    const float* text   = (const float*)d_in[0];
    const float* enc_w1 = (const float*)d_in[1];
    const float* enc_b1 = (const float*)d_in[2];
    const float* enc_w2 = (const float*)d_in[3];
    const float* enc_b2 = (const float*)d_in[4];
    const float* attr   = (const float*)d_in[5];
    const float* dec_w1 = (const float*)d_in[6];
    const float* dec_b1 = (const float*)d_in[7];
    const float* dec_w2 = (const float*)d_in[8];
    const float* dec_b2 = (const float*)d_in[9];

    float* out       = (float*)d_out;
    float* out_field = out;
    float* out_rec   = out + OUT_FIELD_ELEMS;
    float* out_chg   = out + OUT_FIELD_ELEMS + OUT_REC_ELEMS;

    bf16 *Thi, *Tlo, *Hhi, *Hlo, *Fhi, *Flo;
    bf16 *W1hi, *W1lo, *W2hi, *W2lo, *W3hi, *W3lo, *W4hi, *W4lo;
    float* EMB;
    cudaGetSymbolAddress((void**)&Thi,  g_Thi);  cudaGetSymbolAddress((void**)&Tlo,  g_Tlo);
    cudaGetSymbolAddress((void**)&Hhi,  g_Hhi);  cudaGetSymbolAddress((void**)&Hlo,  g_Hlo);
    cudaGetSymbolAddress((void**)&Fhi,  g_Fhi);  cudaGetSymbolAddress((void**)&Flo,  g_Flo);
    cudaGetSymbolAddress((void**)&W1hi, g_W1hi); cudaGetSymbolAddress((void**)&W1lo, g_W1lo);
    cudaGetSymbolAddress((void**)&W2hi, g_W2hi); cudaGetSymbolAddress((void**)&W2lo, g_W2lo);
    cudaGetSymbolAddress((void**)&W3hi, g_W3hi); cudaGetSymbolAddress((void**)&W3lo, g_W3lo);
    cudaGetSymbolAddress((void**)&W4hi, g_W4hi); cudaGetSymbolAddress((void**)&W4lo, g_W4lo);
    cudaGetSymbolAddress((void**)&EMB,  g_EMB);

    // Fused prep (text+weights split, Gram, resets) — one launch
    prep_kernel<<<8705, 256>>>(text, enc_w1, enc_w2, dec_w1, dec_w2, attr);

    // enc1: [M,100p128] @ W1 -> relu -> H (bf16 split), N=256
    mma_gemm<true, true><<<dim3(M_TOK / 128, 4), 256>>>(
        Thi, Tlo, 128, W1hi, W1lo, 128, enc_b1,
        nullptr, Hhi, Hlo, 256, 256, 2);
    // enc2: [M,256] @ W2 -> EMB fp32, N=128
    mma_gemm<false, false><<<dim3(M_TOK / 128, 2), 256>>>(
        Hhi, Hlo, 256, W2hi, W2lo, 256, enc_b2,
        EMB, nullptr, nullptr, 128, 128, 4);

    // Attractor: grouped closed-form dual loop + fused finish
    attractor_kernel<<<M_TOK / 128, 128>>>(EMB, attr, out_field, out_chg);

    // dec1: [M,128] @ W3 -> relu -> H (bf16 split), N=256
    mma_gemm<true, true><<<dim3(M_TOK / 128, 4), 256>>>(
        Fhi, Flo, 128, W3hi, W3lo, 128, dec_b1,
        nullptr, Hhi, Hlo, 256, 256, 2);
    // dec2: [M,256] @ W4 -> out_rec fp32, N=100 (ldc=100)
    mma_gemm<false, false><<<dim3(M_TOK / 128, 2), 256>>>(
        Hhi, Hlo, 256, W4hi, W4lo, 256, dec_b2,
        out_rec, nullptr, nullptr, 100, 100, 4);
}